// round 1
// baseline (speedup 1.0000x reference)
#include <cuda_runtime.h>

// Problem constants
#define BZ 4
#define SEQ 2048
#define DM 1024
#define NH 16
#define HD 64
// derived
#define M_TOT (BZ*SEQ)        // 8192
#define N_TOT (3*DM)          // 3072

// Scratch: Q/K/V in [B, H, S, HD] layout (32 MB each)
__device__ float g_Q[BZ*NH*SEQ*HD];
__device__ float g_K[BZ*NH*SEQ*HD];
__device__ float g_V[BZ*NH*SEQ*HD];

// ---------------------------------------------------------------------------
// Kernel 1: fused QKV GEMM.  C[8192,3072] = x[8192,1024] @ W[1024,3072] + b
// Tiling: 128x128 block tile, BK=16, 256 threads, 8x8 per-thread micro-tile.
// Epilogue scatters into g_Q/g_K/g_V in [B,H,S,HD] layout.
// ---------------------------------------------------------------------------
__global__ __launch_bounds__(256) void qkv_gemm(const float* __restrict__ A,
                                                const float* __restrict__ W,
                                                const float* __restrict__ bias)
{
    __shared__ float As[16][128];   // transposed A tile
    __shared__ float Bs[16][128];

    const int tid = threadIdx.x;
    const int bn  = blockIdx.x;     // 0..23
    const int bm  = blockIdx.y;     // 0..63
    const int ty  = tid >> 4;       // 0..15
    const int tx  = tid & 15;       // 0..15

    float acc[8][8];
    #pragma unroll
    for (int i = 0; i < 8; i++)
        #pragma unroll
        for (int j = 0; j < 8; j++) acc[i][j] = 0.f;

    for (int k0 = 0; k0 < DM; k0 += 16) {
        // Load A tile (128 rows x 16 k) : 512 float4, 2 per thread
        #pragma unroll
        for (int l = 0; l < 2; l++) {
            int idx = tid + l * 256;
            int r   = idx >> 2;          // 0..127
            int kc  = (idx & 3) * 4;     // 0,4,8,12
            float4 a4 = *(const float4*)(A + (size_t)(bm * 128 + r) * DM + k0 + kc);
            As[kc + 0][r] = a4.x;
            As[kc + 1][r] = a4.y;
            As[kc + 2][r] = a4.z;
            As[kc + 3][r] = a4.w;
        }
        // Load B tile (16 k x 128 cols) : 512 float4, 2 per thread
        #pragma unroll
        for (int l = 0; l < 2; l++) {
            int idx = tid + l * 256;
            int kr  = idx >> 5;          // 0..15
            int c   = (idx & 31) * 4;    // 0..124
            *(float4*)&Bs[kr][c] =
                *(const float4*)(W + (size_t)(k0 + kr) * N_TOT + bn * 128 + c);
        }
        __syncthreads();

        #pragma unroll
        for (int kk = 0; kk < 16; kk++) {
            float a[8], b[8];
            #pragma unroll
            for (int i = 0; i < 4; i++) {
                float4 t4 = *(const float4*)&As[kk][ty * 8 + i * 4];
                a[i*4+0] = t4.x; a[i*4+1] = t4.y; a[i*4+2] = t4.z; a[i*4+3] = t4.w;
            }
            #pragma unroll
            for (int j = 0; j < 2; j++) {
                float4 t4 = *(const float4*)&Bs[kk][tx * 8 + j * 4];
                b[j*4+0] = t4.x; b[j*4+1] = t4.y; b[j*4+2] = t4.z; b[j*4+3] = t4.w;
            }
            #pragma unroll
            for (int i = 0; i < 8; i++)
                #pragma unroll
                for (int j = 0; j < 8; j++)
                    acc[i][j] += a[i] * b[j];
        }
        __syncthreads();
    }

    // Epilogue: add bias, scatter into Q/K/V [B,H,S,HD]
    #pragma unroll
    for (int i = 0; i < 8; i++) {
        int m  = bm * 128 + ty * 8 + i;
        int b_ = m >> 11;        // m / 2048
        int s_ = m & 2047;
        #pragma unroll
        for (int j = 0; j < 8; j++) {
            int n = bn * 128 + tx * 8 + j;
            float v = acc[i][j] + bias[n];
            int h = n / 192;
            int r = n - h * 192;
            float* dst = (r < 64) ? g_Q : ((r < 128) ? g_K : g_V);
            dst[((((size_t)b_ * NH + h) * SEQ) + s_) * HD + (r & 63)] = v;
        }
    }
}

// ---------------------------------------------------------------------------
// Kernel 2: causal flash attention, fp32.
// Block: 128 threads, each owns one q row (q tile = 128 rows).
// K/V tiles of 64 rows staged in shared memory; online softmax in registers.
// Grid: (S/128, NH, B)
// ---------------------------------------------------------------------------
__global__ __launch_bounds__(128) void attn_kernel(float* __restrict__ out)
{
    __shared__ float Ks[64 * HD];
    __shared__ float Vs[64 * HD];

    const int t  = threadIdx.x;
    const int qt = blockIdx.x;
    const int h  = blockIdx.y;
    const int b  = blockIdx.z;
    const int row = qt * 128 + t;

    const size_t head_base = (((size_t)b * NH + h) * SEQ) * HD;
    const float* qptr = g_Q + head_base + (size_t)row * HD;

    // q row in registers, pre-scaled by 1/sqrt(hd)
    float4 q4[16];
    #pragma unroll
    for (int i = 0; i < 16; i++) {
        float4 v = ((const float4*)qptr)[i];
        v.x *= 0.125f; v.y *= 0.125f; v.z *= 0.125f; v.w *= 0.125f;
        q4[i] = v;
    }

    float4 o4[16];
    #pragma unroll
    for (int i = 0; i < 16; i++) o4[i] = make_float4(0.f, 0.f, 0.f, 0.f);
    float mrun = -1e30f, l = 0.f;

    const int nkb = qt * 2 + 2;   // causal: only blocks covering k <= row
    const float4* kbase = (const float4*)(g_K + head_base);
    const float4* vbase = (const float4*)(g_V + head_base);

    for (int kb = 0; kb < nkb; kb++) {
        __syncthreads();
        const float4* ksrc = kbase + (size_t)kb * 64 * (HD / 4);
        const float4* vsrc = vbase + (size_t)kb * 64 * (HD / 4);
        #pragma unroll
        for (int i = 0; i < 8; i++) {
            ((float4*)Ks)[t + i * 128] = ksrc[t + i * 128];
            ((float4*)Vs)[t + i * 128] = vsrc[t + i * 128];
        }
        __syncthreads();

        const int rem = row - kb * 64;  // j valid iff j <= rem
        float s[64];
        float mb = -1e30f;
        #pragma unroll 4
        for (int j = 0; j < 64; j++) {
            const float4* kr = (const float4*)(Ks + j * HD);
            float a0 = 0.f, a1 = 0.f, a2 = 0.f, a3 = 0.f;
            #pragma unroll
            for (int kk = 0; kk < 16; kk += 4) {
                float4 k0 = kr[kk + 0], k1 = kr[kk + 1], k2 = kr[kk + 2], k3 = kr[kk + 3];
                a0 += q4[kk+0].x*k0.x + q4[kk+0].y*k0.y + q4[kk+0].z*k0.z + q4[kk+0].w*k0.w;
                a1 += q4[kk+1].x*k1.x + q4[kk+1].y*k1.y + q4[kk+1].z*k1.z + q4[kk+1].w*k1.w;
                a2 += q4[kk+2].x*k2.x + q4[kk+2].y*k2.y + q4[kk+2].z*k2.z + q4[kk+2].w*k2.w;
                a3 += q4[kk+3].x*k3.x + q4[kk+3].y*k3.y + q4[kk+3].z*k3.z + q4[kk+3].w*k3.w;
            }
            float acc = (a0 + a1) + (a2 + a3);
            acc = (j <= rem) ? acc : -1e30f;
            s[j] = acc;
            mb = fmaxf(mb, acc);
        }

        float mnew = fmaxf(mrun, mb);
        float corr = __expf(mrun - mnew);
        l *= corr;
        #pragma unroll
        for (int i = 0; i < 16; i++) {
            o4[i].x *= corr; o4[i].y *= corr; o4[i].z *= corr; o4[i].w *= corr;
        }

        #pragma unroll 2
        for (int j = 0; j < 64; j++) {
            float p = __expf(s[j] - mnew);
            l += p;
            const float4* vr = (const float4*)(Vs + j * HD);
            #pragma unroll
            for (int kk = 0; kk < 16; kk++) {
                float4 v = vr[kk];
                o4[kk].x += p * v.x;
                o4[kk].y += p * v.y;
                o4[kk].z += p * v.z;
                o4[kk].w += p * v.w;
            }
        }
        mrun = mnew;
    }

    const float inv = 1.f / l;
    float* optr = out + ((size_t)b * SEQ + row) * DM + h * HD;
    #pragma unroll
    for (int i = 0; i < 16; i++) {
        float4 v = o4[i];
        v.x *= inv; v.y *= inv; v.z *= inv; v.w *= inv;
        ((float4*)optr)[i] = v;
    }
}

// ---------------------------------------------------------------------------
extern "C" void kernel_launch(void* const* d_in, const int* in_sizes, int n_in,
                              void* d_out, int out_size)
{
    (void)in_sizes; (void)n_in; (void)out_size;
    const float* x    = (const float*)d_in[0];   // [B, S, D]
    const float* Wqkv = (const float*)d_in[1];   // [D, 3D]
    const float* bqkv = (const float*)d_in[2];   // [3D]
    float* out = (float*)d_out;                  // [B, S, D]

    dim3 ggrid(N_TOT / 128, M_TOT / 128);        // (24, 64)
    qkv_gemm<<<ggrid, 256>>>(x, Wqkv, bqkv);

    dim3 agrid(SEQ / 128, NH, BZ);               // (16, 16, 4)
    attn_kernel<<<agrid, 128>>>(out);
}

// round 3
// speedup vs baseline: 1.3688x; 1.3688x over previous
#include <cuda_runtime.h>
#include <cstdint>

// Problem constants
#define BZ 4
#define SEQ 2048
#define DM 1024
#define NH 16
#define HD 64
#define M_TOT (BZ*SEQ)        // 8192
#define N_TOT (3*DM)          // 3072

// Scratch: Q/K/V in [B, H, S, HD] layout
__device__ float g_Q[BZ*NH*SEQ*HD];
__device__ float g_K[BZ*NH*SEQ*HD];
__device__ float g_V[BZ*NH*SEQ*HD];

// ---------------------------------------------------------------------------
// helpers
// ---------------------------------------------------------------------------
__device__ __forceinline__ uint32_t f2tf32(float f){
    uint32_t u; asm("cvt.rna.tf32.f32 %0, %1;" : "=r"(u) : "f"(f)); return u;
}
__device__ __forceinline__ void mma8(float* c, const uint32_t* a, const uint32_t* b){
    asm volatile("mma.sync.aligned.m16n8k8.row.col.f32.tf32.tf32.f32 "
        "{%0,%1,%2,%3}, {%4,%5,%6,%7}, {%8,%9}, {%0,%1,%2,%3};"
        : "+f"(c[0]), "+f"(c[1]), "+f"(c[2]), "+f"(c[3])
        : "r"(a[0]), "r"(a[1]), "r"(a[2]), "r"(a[3]), "r"(b[0]), "r"(b[1]));
}

// ---------------------------------------------------------------------------
// Kernel 1: QKV GEMM via mma.sync tf32.
// C[8192,3072] = x[8192,1024] @ W[1024,3072] + b, scatter to g_Q/g_K/g_V.
// CTA tile 128x128, BK=16, 8 warps (4M x 2N), warp tile 32x64, double buffer.
// SMEM pads: A stride 20, B stride 136 -> conflict-free fragment LDS.
// ---------------------------------------------------------------------------
#define APAD 20
#define BPAD 136

__global__ __launch_bounds__(256, 2) void qkv_gemm_mma(const float* __restrict__ A,
                                                       const float* __restrict__ W,
                                                       const float* __restrict__ bias)
{
    __shared__ __align__(16) float sA[2][128 * APAD];
    __shared__ __align__(16) float sB[2][16 * BPAD];

    const int tid  = threadIdx.x;
    const int wid  = tid >> 5;
    const int lane = tid & 31;
    const int wrow = wid & 3;     // m offset = wrow*32
    const int wcol = wid >> 2;    // n offset = wcol*64
    const int bm = blockIdx.y, bn = blockIdx.x;

    const float* Ablk = A + (size_t)(bm * 128) * DM;
    const float* Wblk = W + bn * 128;

    // gmem load mapping: 512 float4 per tile, 2 per thread (idx = 2*tid + l)
    const int i0 = 2 * tid, i1 = 2 * tid + 1;
    const float* ap0 = Ablk + (size_t)(i0 >> 2) * DM + (i0 & 3) * 4;
    const float* ap1 = Ablk + (size_t)(i1 >> 2) * DM + (i1 & 3) * 4;
    const float* bp0 = Wblk + (size_t)(i0 >> 5) * N_TOT + (i0 & 31) * 4;
    const float* bp1 = Wblk + (size_t)(i1 >> 5) * N_TOT + (i1 & 31) * 4;
    const int sa0 = (i0 >> 2) * APAD + (i0 & 3) * 4;
    const int sa1 = (i1 >> 2) * APAD + (i1 & 3) * 4;
    const int sb0 = (i0 >> 5) * BPAD + (i0 & 31) * 4;
    const int sb1 = (i1 >> 5) * BPAD + (i1 & 31) * 4;

    float acc[2][8][4];
    #pragma unroll
    for (int mt = 0; mt < 2; mt++)
        #pragma unroll
        for (int j = 0; j < 8; j++)
            #pragma unroll
            for (int e = 0; e < 4; e++) acc[mt][j][e] = 0.f;

    float4 ra0, ra1, rb0, rb1;

    auto gload = [&](int k0) {
        ra0 = *(const float4*)(ap0 + k0);
        ra1 = *(const float4*)(ap1 + k0);
        rb0 = *(const float4*)(bp0 + (size_t)k0 * N_TOT);
        rb1 = *(const float4*)(bp1 + (size_t)k0 * N_TOT);
    };
    auto sts = [&](int buf) {
        float* pa = &sA[buf][0];
        float* pb = &sB[buf][0];
        // A: two float2 stores per float4 (8B-aligned under stride 20)
        *(float2*)(pa + sa0)     = make_float2(__uint_as_float(f2tf32(ra0.x)), __uint_as_float(f2tf32(ra0.y)));
        *(float2*)(pa + sa0 + 2) = make_float2(__uint_as_float(f2tf32(ra0.z)), __uint_as_float(f2tf32(ra0.w)));
        *(float2*)(pa + sa1)     = make_float2(__uint_as_float(f2tf32(ra1.x)), __uint_as_float(f2tf32(ra1.y)));
        *(float2*)(pa + sa1 + 2) = make_float2(__uint_as_float(f2tf32(ra1.z)), __uint_as_float(f2tf32(ra1.w)));
        // B: float4 stores (16B-aligned under stride 136)
        float4 t0 = make_float4(__uint_as_float(f2tf32(rb0.x)), __uint_as_float(f2tf32(rb0.y)),
                                __uint_as_float(f2tf32(rb0.z)), __uint_as_float(f2tf32(rb0.w)));
        float4 t1 = make_float4(__uint_as_float(f2tf32(rb1.x)), __uint_as_float(f2tf32(rb1.y)),
                                __uint_as_float(f2tf32(rb1.z)), __uint_as_float(f2tf32(rb1.w)));
        *(float4*)(pb + sb0) = t0;
        *(float4*)(pb + sb1) = t1;
    };

    gload(0);
    sts(0);
    __syncthreads();

    #pragma unroll 1
    for (int kb = 0; kb < DM / 16; kb++) {
        const int buf = kb & 1;
        if (kb < DM / 16 - 1) gload((kb + 1) * 16);

        // fragment base pointers (conflict-free scalar LDS)
        const float* pa = &sA[buf][0] + (wrow * 32 + (lane >> 2)) * APAD + (lane & 3);
        const float* pb = &sB[buf][0] + (lane & 3) * BPAD + wcol * 64 + (lane >> 2);

        #pragma unroll
        for (int kt = 0; kt < 2; kt++) {
            uint32_t af[2][4];
            #pragma unroll
            for (int mt = 0; mt < 2; mt++) {
                const float* p = pa + mt * 16 * APAD + kt * 8;
                af[mt][0] = __float_as_uint(p[0]);
                af[mt][1] = __float_as_uint(p[8 * APAD]);
                af[mt][2] = __float_as_uint(p[4]);
                af[mt][3] = __float_as_uint(p[8 * APAD + 4]);
            }
            uint32_t bf[8][2];
            #pragma unroll
            for (int j = 0; j < 8; j++) {
                const float* q = pb + kt * 8 * BPAD + j * 8;
                bf[j][0] = __float_as_uint(q[0]);
                bf[j][1] = __float_as_uint(q[4 * BPAD]);
            }
            #pragma unroll
            for (int mt = 0; mt < 2; mt++)
                #pragma unroll
                for (int j = 0; j < 8; j++)
                    mma8(acc[mt][j], af[mt], bf[j]);
        }

        if (kb < DM / 16 - 1) sts(buf ^ 1);
        __syncthreads();
    }

    // Epilogue: bias + scatter to Q/K/V (float2 pairs; n0 even => no head crossing)
    #pragma unroll
    for (int mt = 0; mt < 2; mt++) {
        #pragma unroll
        for (int j = 0; j < 8; j++) {
            int row = wrow * 32 + mt * 16 + (lane >> 2);
            int n0  = bn * 128 + wcol * 64 + j * 8 + (lane & 3) * 2;
            float bx = __ldg(&bias[n0]), by = __ldg(&bias[n0 + 1]);
            int h = n0 / 192;
            int r = n0 - h * 192;
            float* dst = (r < 64) ? g_Q : ((r < 128) ? g_K : g_V);
            #pragma unroll
            for (int half = 0; half < 2; half++) {
                int m  = bm * 128 + row + half * 8;
                int b_ = m >> 11;
                int s_ = m & 2047;
                size_t o = ((((size_t)b_ * NH + h) * SEQ) + s_) * HD + (r & 63);
                *(float2*)(dst + o) = make_float2(acc[mt][j][half * 2] + bx,
                                                  acc[mt][j][half * 2 + 1] + by);
            }
        }
    }
}

// ---------------------------------------------------------------------------
// Kernel 2: causal flash attention, fp32 (unchanged, known-good).
// ---------------------------------------------------------------------------
__global__ __launch_bounds__(128) void attn_kernel(float* __restrict__ out)
{
    __shared__ float Ks[64 * HD];
    __shared__ float Vs[64 * HD];

    const int t  = threadIdx.x;
    const int qt = blockIdx.x;
    const int h  = blockIdx.y;
    const int b  = blockIdx.z;
    const int row = qt * 128 + t;

    const size_t head_base = (((size_t)b * NH + h) * SEQ) * HD;
    const float* qptr = g_Q + head_base + (size_t)row * HD;

    float4 q4[16];
    #pragma unroll
    for (int i = 0; i < 16; i++) {
        float4 v = ((const float4*)qptr)[i];
        v.x *= 0.125f; v.y *= 0.125f; v.z *= 0.125f; v.w *= 0.125f;
        q4[i] = v;
    }

    float4 o4[16];
    #pragma unroll
    for (int i = 0; i < 16; i++) o4[i] = make_float4(0.f, 0.f, 0.f, 0.f);
    float mrun = -1e30f, l = 0.f;

    const int nkb = qt * 2 + 2;
    const float4* kbase = (const float4*)(g_K + head_base);
    const float4* vbase = (const float4*)(g_V + head_base);

    for (int kb = 0; kb < nkb; kb++) {
        __syncthreads();
        const float4* ksrc = kbase + (size_t)kb * 64 * (HD / 4);
        const float4* vsrc = vbase + (size_t)kb * 64 * (HD / 4);
        #pragma unroll
        for (int i = 0; i < 8; i++) {
            ((float4*)Ks)[t + i * 128] = ksrc[t + i * 128];
            ((float4*)Vs)[t + i * 128] = vsrc[t + i * 128];
        }
        __syncthreads();

        const int rem = row - kb * 64;
        float s[64];
        float mb = -1e30f;
        #pragma unroll 4
        for (int j = 0; j < 64; j++) {
            const float4* kr = (const float4*)(Ks + j * HD);
            float a0 = 0.f, a1 = 0.f, a2 = 0.f, a3 = 0.f;
            #pragma unroll
            for (int kk = 0; kk < 16; kk += 4) {
                float4 k0 = kr[kk + 0], k1 = kr[kk + 1], k2 = kr[kk + 2], k3 = kr[kk + 3];
                a0 += q4[kk+0].x*k0.x + q4[kk+0].y*k0.y + q4[kk+0].z*k0.z + q4[kk+0].w*k0.w;
                a1 += q4[kk+1].x*k1.x + q4[kk+1].y*k1.y + q4[kk+1].z*k1.z + q4[kk+1].w*k1.w;
                a2 += q4[kk+2].x*k2.x + q4[kk+2].y*k2.y + q4[kk+2].z*k2.z + q4[kk+2].w*k2.w;
                a3 += q4[kk+3].x*k3.x + q4[kk+3].y*k3.y + q4[kk+3].z*k3.z + q4[kk+3].w*k3.w;
            }
            float acc = (a0 + a1) + (a2 + a3);
            acc = (j <= rem) ? acc : -1e30f;
            s[j] = acc;
            mb = fmaxf(mb, acc);
        }

        float mnew = fmaxf(mrun, mb);
        float corr = __expf(mrun - mnew);
        l *= corr;
        #pragma unroll
        for (int i = 0; i < 16; i++) {
            o4[i].x *= corr; o4[i].y *= corr; o4[i].z *= corr; o4[i].w *= corr;
        }

        #pragma unroll 2
        for (int j = 0; j < 64; j++) {
            float p = __expf(s[j] - mnew);
            l += p;
            const float4* vr = (const float4*)(Vs + j * HD);
            #pragma unroll
            for (int kk = 0; kk < 16; kk++) {
                float4 v = vr[kk];
                o4[kk].x += p * v.x;
                o4[kk].y += p * v.y;
                o4[kk].z += p * v.z;
                o4[kk].w += p * v.w;
            }
        }
        mrun = mnew;
    }

    const float inv = 1.f / l;
    float* optr = out + ((size_t)b * SEQ + row) * DM + h * HD;
    #pragma unroll
    for (int i = 0; i < 16; i++) {
        float4 v = o4[i];
        v.x *= inv; v.y *= inv; v.z *= inv; v.w *= inv;
        ((float4*)optr)[i] = v;
    }
}

// ---------------------------------------------------------------------------
extern "C" void kernel_launch(void* const* d_in, const int* in_sizes, int n_in,
                              void* d_out, int out_size)
{
    (void)in_sizes; (void)n_in; (void)out_size;
    const float* x    = (const float*)d_in[0];   // [B, S, D]
    const float* Wqkv = (const float*)d_in[1];   // [D, 3D]
    const float* bqkv = (const float*)d_in[2];   // [3D]
    float* out = (float*)d_out;                  // [B, S, D]

    dim3 ggrid(N_TOT / 128, M_TOT / 128);        // (24, 64)
    qkv_gemm_mma<<<ggrid, 256>>>(x, Wqkv, bqkv);

    dim3 agrid(SEQ / 128, NH, BZ);               // (16, 16, 4)
    attn_kernel<<<agrid, 128>>>(out);
}

// round 4
// speedup vs baseline: 3.1782x; 2.3218x over previous
#include <cuda_runtime.h>
#include <cstdint>

// Problem constants
#define BZ 4
#define SEQ 2048
#define DM 1024
#define NH 16
#define HD 64
#define M_TOT (BZ*SEQ)        // 8192
#define N_TOT (3*DM)          // 3072

// Scratch: Q/K/V in [B, H, S, HD] layout
__device__ float g_Q[BZ*NH*SEQ*HD];
__device__ float g_K[BZ*NH*SEQ*HD];
__device__ float g_V[BZ*NH*SEQ*HD];

// ---------------------------------------------------------------------------
// helpers
// ---------------------------------------------------------------------------
__device__ __forceinline__ uint32_t f2tf32(float f){
    uint32_t u; asm("cvt.rna.tf32.f32 %0, %1;" : "=r"(u) : "f"(f)); return u;
}
__device__ __forceinline__ void mma8(float* c, const uint32_t* a, const uint32_t* b){
    asm volatile("mma.sync.aligned.m16n8k8.row.col.f32.tf32.tf32.f32 "
        "{%0,%1,%2,%3}, {%4,%5,%6,%7}, {%8,%9}, {%0,%1,%2,%3};"
        : "+f"(c[0]), "+f"(c[1]), "+f"(c[2]), "+f"(c[3])
        : "r"(a[0]), "r"(a[1]), "r"(a[2]), "r"(a[3]), "r"(b[0]), "r"(b[1]));
}

// ---------------------------------------------------------------------------
// Kernel 1: QKV GEMM via mma.sync tf32 (unchanged from round 3, known-good).
// ---------------------------------------------------------------------------
#define APAD 20
#define BPAD 136

__global__ __launch_bounds__(256, 2) void qkv_gemm_mma(const float* __restrict__ A,
                                                       const float* __restrict__ W,
                                                       const float* __restrict__ bias)
{
    __shared__ __align__(16) float sA[2][128 * APAD];
    __shared__ __align__(16) float sB[2][16 * BPAD];

    const int tid  = threadIdx.x;
    const int wid  = tid >> 5;
    const int lane = tid & 31;
    const int wrow = wid & 3;
    const int wcol = wid >> 2;
    const int bm = blockIdx.y, bn = blockIdx.x;

    const float* Ablk = A + (size_t)(bm * 128) * DM;
    const float* Wblk = W + bn * 128;

    const int i0 = 2 * tid, i1 = 2 * tid + 1;
    const float* ap0 = Ablk + (size_t)(i0 >> 2) * DM + (i0 & 3) * 4;
    const float* ap1 = Ablk + (size_t)(i1 >> 2) * DM + (i1 & 3) * 4;
    const float* bp0 = Wblk + (size_t)(i0 >> 5) * N_TOT + (i0 & 31) * 4;
    const float* bp1 = Wblk + (size_t)(i1 >> 5) * N_TOT + (i1 & 31) * 4;
    const int sa0 = (i0 >> 2) * APAD + (i0 & 3) * 4;
    const int sa1 = (i1 >> 2) * APAD + (i1 & 3) * 4;
    const int sb0 = (i0 >> 5) * BPAD + (i0 & 31) * 4;
    const int sb1 = (i1 >> 5) * BPAD + (i1 & 31) * 4;

    float acc[2][8][4];
    #pragma unroll
    for (int mt = 0; mt < 2; mt++)
        #pragma unroll
        for (int j = 0; j < 8; j++)
            #pragma unroll
            for (int e = 0; e < 4; e++) acc[mt][j][e] = 0.f;

    float4 ra0, ra1, rb0, rb1;

    auto gload = [&](int k0) {
        ra0 = *(const float4*)(ap0 + k0);
        ra1 = *(const float4*)(ap1 + k0);
        rb0 = *(const float4*)(bp0 + (size_t)k0 * N_TOT);
        rb1 = *(const float4*)(bp1 + (size_t)k0 * N_TOT);
    };
    auto sts = [&](int buf) {
        float* pa = &sA[buf][0];
        float* pb = &sB[buf][0];
        *(float2*)(pa + sa0)     = make_float2(__uint_as_float(f2tf32(ra0.x)), __uint_as_float(f2tf32(ra0.y)));
        *(float2*)(pa + sa0 + 2) = make_float2(__uint_as_float(f2tf32(ra0.z)), __uint_as_float(f2tf32(ra0.w)));
        *(float2*)(pa + sa1)     = make_float2(__uint_as_float(f2tf32(ra1.x)), __uint_as_float(f2tf32(ra1.y)));
        *(float2*)(pa + sa1 + 2) = make_float2(__uint_as_float(f2tf32(ra1.z)), __uint_as_float(f2tf32(ra1.w)));
        float4 t0 = make_float4(__uint_as_float(f2tf32(rb0.x)), __uint_as_float(f2tf32(rb0.y)),
                                __uint_as_float(f2tf32(rb0.z)), __uint_as_float(f2tf32(rb0.w)));
        float4 t1 = make_float4(__uint_as_float(f2tf32(rb1.x)), __uint_as_float(f2tf32(rb1.y)),
                                __uint_as_float(f2tf32(rb1.z)), __uint_as_float(f2tf32(rb1.w)));
        *(float4*)(pb + sb0) = t0;
        *(float4*)(pb + sb1) = t1;
    };

    gload(0);
    sts(0);
    __syncthreads();

    #pragma unroll 1
    for (int kb = 0; kb < DM / 16; kb++) {
        const int buf = kb & 1;
        if (kb < DM / 16 - 1) gload((kb + 1) * 16);

        const float* pa = &sA[buf][0] + (wrow * 32 + (lane >> 2)) * APAD + (lane & 3);
        const float* pb = &sB[buf][0] + (lane & 3) * BPAD + wcol * 64 + (lane >> 2);

        #pragma unroll
        for (int kt = 0; kt < 2; kt++) {
            uint32_t af[2][4];
            #pragma unroll
            for (int mt = 0; mt < 2; mt++) {
                const float* p = pa + mt * 16 * APAD + kt * 8;
                af[mt][0] = __float_as_uint(p[0]);
                af[mt][1] = __float_as_uint(p[8 * APAD]);
                af[mt][2] = __float_as_uint(p[4]);
                af[mt][3] = __float_as_uint(p[8 * APAD + 4]);
            }
            uint32_t bf[8][2];
            #pragma unroll
            for (int j = 0; j < 8; j++) {
                const float* q = pb + kt * 8 * BPAD + j * 8;
                bf[j][0] = __float_as_uint(q[0]);
                bf[j][1] = __float_as_uint(q[4 * BPAD]);
            }
            #pragma unroll
            for (int mt = 0; mt < 2; mt++)
                #pragma unroll
                for (int j = 0; j < 8; j++)
                    mma8(acc[mt][j], af[mt], bf[j]);
        }

        if (kb < DM / 16 - 1) sts(buf ^ 1);
        __syncthreads();
    }

    #pragma unroll
    for (int mt = 0; mt < 2; mt++) {
        #pragma unroll
        for (int j = 0; j < 8; j++) {
            int row = wrow * 32 + mt * 16 + (lane >> 2);
            int n0  = bn * 128 + wcol * 64 + j * 8 + (lane & 3) * 2;
            float bx = __ldg(&bias[n0]), by = __ldg(&bias[n0 + 1]);
            int h = n0 / 192;
            int r = n0 - h * 192;
            float* dst = (r < 64) ? g_Q : ((r < 128) ? g_K : g_V);
            #pragma unroll
            for (int half = 0; half < 2; half++) {
                int m  = bm * 128 + row + half * 8;
                int b_ = m >> 11;
                int s_ = m & 2047;
                size_t o = ((((size_t)b_ * NH + h) * SEQ) + s_) * HD + (r & 63);
                *(float2*)(dst + o) = make_float2(acc[mt][j][half * 2] + bx,
                                                  acc[mt][j][half * 2 + 1] + by);
            }
        }
    }
}

// ---------------------------------------------------------------------------
// Kernel 2: causal flash attention on tensor cores (mma.sync tf32).
// CTA: 128 q-rows of one (b,h); 8 warps x 16 rows. KV tiles of 64 keys.
// SMEM pads: Q/P stride 68, K stride 68, V stride 72 -> conflict-free LDS.
// ---------------------------------------------------------------------------
#define QP 68
#define VP 72
#define L2E 1.44269504f

__global__ __launch_bounds__(256, 1) void attn_mma(float* __restrict__ out)
{
    extern __shared__ float sm[];
    float* Ps = sm;                    // [128][QP]  (Q tile, then P tiles)
    float* Ks = sm + 128 * QP;         // [64][QP]
    float* Vs = Ks + 64 * QP;          // [64][VP]

    const int tid  = threadIdx.x;
    const int wid  = tid >> 5;
    const int lane = tid & 31;
    const int g = lane >> 2, t = lane & 3;
    const int qt = blockIdx.x, h = blockIdx.y, b = blockIdx.z;
    const int wb = wid * 16;                 // warp q-row base in tile
    const int row0 = qt * 128 + wb + g;      // global q row (other: +8)

    const size_t head_base = (((size_t)b * NH + h) * SEQ) * HD;

    // Stage Q tile (x0.125, tf32) into Ps: 2048 float4, 8 per thread
    {
        const float* qsrc = g_Q + head_base + (size_t)qt * 128 * HD;
        #pragma unroll
        for (int i = 0; i < 8; i++) {
            int idx = tid + i * 256;
            int r = idx >> 4, c = (idx & 15) * 4;
            float4 v = *(const float4*)(qsrc + r * HD + c);
            float4 o;
            o.x = __uint_as_float(f2tf32(v.x * 0.125f));
            o.y = __uint_as_float(f2tf32(v.y * 0.125f));
            o.z = __uint_as_float(f2tf32(v.z * 0.125f));
            o.w = __uint_as_float(f2tf32(v.w * 0.125f));
            *(float4*)(Ps + r * QP + c) = o;
        }
    }
    __syncthreads();

    // Q A-fragments (per-warp 16 rows x 64 d) -> 8 k-tiles x 4 regs
    uint32_t aq[8][4];
    {
        const float* p = Ps + (wb + g) * QP + t;
        #pragma unroll
        for (int kt = 0; kt < 8; kt++) {
            aq[kt][0] = __float_as_uint(p[kt * 8]);
            aq[kt][1] = __float_as_uint(p[8 * QP + kt * 8]);
            aq[kt][2] = __float_as_uint(p[kt * 8 + 4]);
            aq[kt][3] = __float_as_uint(p[8 * QP + kt * 8 + 4]);
        }
    }

    float o[8][4];
    #pragma unroll
    for (int nt = 0; nt < 8; nt++)
        #pragma unroll
        for (int e = 0; e < 4; e++) o[nt][e] = 0.f;
    float m0 = -1e30f, m1 = -1e30f, l0 = 0.f, l1 = 0.f;

    const int nkb = qt * 2 + 2;
    const float* kbase = g_K + head_base;
    const float* vbase = g_V + head_base;

    #pragma unroll 1
    for (int kb = 0; kb < nkb; kb++) {
        __syncthreads();   // previous Ks/Vs fully consumed
        // load K,V tiles (tf32) : 1024 float4 each... 64*64 floats = 1024 f4 total per tensor
        {
            const float* ksrc = kbase + (size_t)kb * 64 * HD;
            const float* vsrc = vbase + (size_t)kb * 64 * HD;
            #pragma unroll
            for (int i = 0; i < 4; i++) {
                int idx = tid + i * 256;
                int r = idx >> 4, c = (idx & 15) * 4;
                float4 kv = *(const float4*)(ksrc + r * HD + c);
                float4 vv = *(const float4*)(vsrc + r * HD + c);
                float4 ko, vo;
                ko.x = __uint_as_float(f2tf32(kv.x)); ko.y = __uint_as_float(f2tf32(kv.y));
                ko.z = __uint_as_float(f2tf32(kv.z)); ko.w = __uint_as_float(f2tf32(kv.w));
                vo.x = __uint_as_float(f2tf32(vv.x)); vo.y = __uint_as_float(f2tf32(vv.y));
                vo.z = __uint_as_float(f2tf32(vv.z)); vo.w = __uint_as_float(f2tf32(vv.w));
                *(float4*)(Ks + r * QP + c) = ko;
                *(float4*)(Vs + r * VP + c) = vo;
            }
        }
        __syncthreads();

        // per-warp full-mask skip (all cols > all rows of this warp)
        if (kb * 64 > qt * 128 + wb + 15) continue;

        // ---- QK^T: S[16 x 64] ----
        float s[8][4];
        #pragma unroll
        for (int nt = 0; nt < 8; nt++)
            #pragma unroll
            for (int e = 0; e < 4; e++) s[nt][e] = 0.f;

        #pragma unroll
        for (int kt = 0; kt < 8; kt++) {
            #pragma unroll
            for (int nt = 0; nt < 8; nt++) {
                uint32_t bk[2];
                const float* kp = Ks + (nt * 8 + g) * QP + kt * 8 + t;
                bk[0] = __float_as_uint(kp[0]);
                bk[1] = __float_as_uint(kp[4]);
                mma8(s[nt], aq[kt], bk);
            }
        }

        // causal mask (only needed on/near the diagonal for this warp)
        if (kb * 64 + 63 > qt * 128 + wb) {
            #pragma unroll
            for (int nt = 0; nt < 8; nt++) {
                int col = kb * 64 + nt * 8 + 2 * t;
                if (col     > row0)     s[nt][0] = -1e30f;
                if (col + 1 > row0)     s[nt][1] = -1e30f;
                if (col     > row0 + 8) s[nt][2] = -1e30f;
                if (col + 1 > row0 + 8) s[nt][3] = -1e30f;
            }
        }

        // ---- online softmax ----
        float mb0 = -1e30f, mb1 = -1e30f;
        #pragma unroll
        for (int nt = 0; nt < 8; nt++) {
            mb0 = fmaxf(mb0, fmaxf(s[nt][0], s[nt][1]));
            mb1 = fmaxf(mb1, fmaxf(s[nt][2], s[nt][3]));
        }
        mb0 = fmaxf(mb0, __shfl_xor_sync(0xffffffffu, mb0, 1));
        mb0 = fmaxf(mb0, __shfl_xor_sync(0xffffffffu, mb0, 2));
        mb1 = fmaxf(mb1, __shfl_xor_sync(0xffffffffu, mb1, 1));
        mb1 = fmaxf(mb1, __shfl_xor_sync(0xffffffffu, mb1, 2));

        float mn0 = fmaxf(m0, mb0), mn1 = fmaxf(m1, mb1);
        float corr0 = exp2f((m0 - mn0) * L2E);
        float corr1 = exp2f((m1 - mn1) * L2E);

        float ls0 = 0.f, ls1 = 0.f;
        float* pw0 = Ps + (wb + g) * QP + 2 * t;
        float* pw1 = Ps + (wb + g + 8) * QP + 2 * t;
        #pragma unroll
        for (int nt = 0; nt < 8; nt++) {
            float p0 = exp2f((s[nt][0] - mn0) * L2E);
            float p1 = exp2f((s[nt][1] - mn0) * L2E);
            float p2 = exp2f((s[nt][2] - mn1) * L2E);
            float p3 = exp2f((s[nt][3] - mn1) * L2E);
            ls0 += p0 + p1;
            ls1 += p2 + p3;
            *(float2*)(pw0 + nt * 8) = make_float2(__uint_as_float(f2tf32(p0)),
                                                   __uint_as_float(f2tf32(p1)));
            *(float2*)(pw1 + nt * 8) = make_float2(__uint_as_float(f2tf32(p2)),
                                                   __uint_as_float(f2tf32(p3)));
        }
        ls0 += __shfl_xor_sync(0xffffffffu, ls0, 1);
        ls0 += __shfl_xor_sync(0xffffffffu, ls0, 2);
        ls1 += __shfl_xor_sync(0xffffffffu, ls1, 1);
        ls1 += __shfl_xor_sync(0xffffffffu, ls1, 2);
        l0 = l0 * corr0 + ls0;
        l1 = l1 * corr1 + ls1;
        m0 = mn0; m1 = mn1;

        #pragma unroll
        for (int nt = 0; nt < 8; nt++) {
            o[nt][0] *= corr0; o[nt][1] *= corr0;
            o[nt][2] *= corr1; o[nt][3] *= corr1;
        }

        __syncwarp();

        // ---- PV: O[16 x 64] += P[16 x 64keys] @ V[64keys x 64d] ----
        const float* pr = Ps + (wb + g) * QP + t;
        #pragma unroll
        for (int kt = 0; kt < 8; kt++) {
            uint32_t ap[4];
            ap[0] = __float_as_uint(pr[kt * 8]);
            ap[1] = __float_as_uint(pr[8 * QP + kt * 8]);
            ap[2] = __float_as_uint(pr[kt * 8 + 4]);
            ap[3] = __float_as_uint(pr[8 * QP + kt * 8 + 4]);
            #pragma unroll
            for (int nt = 0; nt < 8; nt++) {
                uint32_t bv[2];
                const float* vp = Vs + (kt * 8 + t) * VP + nt * 8 + g;
                bv[0] = __float_as_uint(vp[0]);
                bv[1] = __float_as_uint(vp[4 * VP]);
                mma8(o[nt], ap, bv);
            }
        }
        __syncwarp();   // P reads done before next block overwrites (same warp, ordering only)
    }

    // ---- write out: out[b][s][h*64 + d] ----
    const float inv0 = 1.f / l0, inv1 = 1.f / l1;
    float* op0 = out + ((size_t)b * SEQ + row0) * DM + h * HD + 2 * t;
    float* op1 = out + ((size_t)b * SEQ + row0 + 8) * DM + h * HD + 2 * t;
    #pragma unroll
    for (int nt = 0; nt < 8; nt++) {
        *(float2*)(op0 + nt * 8) = make_float2(o[nt][0] * inv0, o[nt][1] * inv0);
        *(float2*)(op1 + nt * 8) = make_float2(o[nt][2] * inv1, o[nt][3] * inv1);
    }
}

// ---------------------------------------------------------------------------
extern "C" void kernel_launch(void* const* d_in, const int* in_sizes, int n_in,
                              void* d_out, int out_size)
{
    (void)in_sizes; (void)n_in; (void)out_size;
    const float* x    = (const float*)d_in[0];   // [B, S, D]
    const float* Wqkv = (const float*)d_in[1];   // [D, 3D]
    const float* bqkv = (const float*)d_in[2];   // [3D]
    float* out = (float*)d_out;                  // [B, S, D]

    dim3 ggrid(N_TOT / 128, M_TOT / 128);        // (24, 64)
    qkv_gemm_mma<<<ggrid, 256>>>(x, Wqkv, bqkv);

    const int attn_smem = (128 * QP + 64 * QP + 64 * VP) * 4;  // 70656 B
    cudaFuncSetAttribute(attn_mma, cudaFuncAttributeMaxDynamicSharedMemorySize, attn_smem);
    dim3 agrid(SEQ / 128, NH, BZ);               // (16, 16, 4)
    attn_mma<<<agrid, 256, attn_smem>>>(out);
}

// round 5
// speedup vs baseline: 3.6118x; 1.1365x over previous
#include <cuda_runtime.h>
#include <cstdint>

// Problem constants
#define BZ 4
#define SEQ 2048
#define DM 1024
#define NH 16
#define HD 64
#define M_TOT (BZ*SEQ)        // 8192
#define N_TOT (3*DM)          // 3072

// Scratch: Q/K/V in [B, H, S, HD] layout
__device__ float g_Q[BZ*NH*SEQ*HD];
__device__ float g_K[BZ*NH*SEQ*HD];
__device__ float g_V[BZ*NH*SEQ*HD];

// ---------------------------------------------------------------------------
// helpers
// ---------------------------------------------------------------------------
__device__ __forceinline__ uint32_t f2tf32(float f){
    uint32_t u; asm("cvt.rna.tf32.f32 %0, %1;" : "=r"(u) : "f"(f)); return u;
}
__device__ __forceinline__ void mma8(float* c, const uint32_t* a, const uint32_t* b){
    asm volatile("mma.sync.aligned.m16n8k8.row.col.f32.tf32.tf32.f32 "
        "{%0,%1,%2,%3}, {%4,%5,%6,%7}, {%8,%9}, {%0,%1,%2,%3};"
        : "+f"(c[0]), "+f"(c[1]), "+f"(c[2]), "+f"(c[3])
        : "r"(a[0]), "r"(a[1]), "r"(a[2]), "r"(a[3]), "r"(b[0]), "r"(b[1]));
}

// ---------------------------------------------------------------------------
// Kernel 1: QKV GEMM via mma.sync tf32.
// CTA tile 256(M) x 128(N), BK=16, 8 warps as 4M x 2N, warp tile 64x64.
// Double-buffered dynamic SMEM (58KB). A stride 20, B stride 136.
// ---------------------------------------------------------------------------
#define APAD 20
#define BPAD 136
#define TMG 256
#define TNG 128

__global__ __launch_bounds__(256, 1) void qkv_gemm_mma(const float* __restrict__ A,
                                                       const float* __restrict__ W,
                                                       const float* __restrict__ bias)
{
    extern __shared__ float smg[];
    float* sA = smg;                       // [2][256*APAD]
    float* sB = smg + 2 * TMG * APAD;      // [2][16*BPAD]

    const int tid  = threadIdx.x;
    const int wid  = tid >> 5;
    const int lane = tid & 31;
    const int g = lane >> 2, t = lane & 3;
    const int wrow = wid & 3;     // m offset = wrow*64
    const int wcol = wid >> 2;    // n offset = wcol*64
    const int bm = blockIdx.y, bn = blockIdx.x;

    const float* Ablk = A + (size_t)(bm * TMG) * DM;
    const float* Wblk = W + bn * TNG;

    // load mapping: A 1024 f4 (4/thread), B 512 f4 (2/thread)
    int ar[4], akc[4], sa[4];
    #pragma unroll
    for (int l = 0; l < 4; l++) {
        int idx = tid + l * 256;
        ar[l]  = idx >> 2;
        akc[l] = (idx & 3) * 4;
        sa[l]  = ar[l] * APAD + akc[l];
    }
    int bkr[2], bc[2], sb[2];
    #pragma unroll
    for (int l = 0; l < 2; l++) {
        int idx = tid + l * 256;
        bkr[l] = idx >> 5;
        bc[l]  = (idx & 31) * 4;
        sb[l]  = bkr[l] * BPAD + bc[l];
    }

    float acc[4][8][4];
    #pragma unroll
    for (int mt = 0; mt < 4; mt++)
        #pragma unroll
        for (int nt = 0; nt < 8; nt++)
            #pragma unroll
            for (int e = 0; e < 4; e++) acc[mt][nt][e] = 0.f;

    float4 ra[4], rb[2];

    auto gload = [&](int k0) {
        #pragma unroll
        for (int l = 0; l < 4; l++)
            ra[l] = *(const float4*)(Ablk + (size_t)ar[l] * DM + k0 + akc[l]);
        #pragma unroll
        for (int l = 0; l < 2; l++)
            rb[l] = *(const float4*)(Wblk + (size_t)(k0 + bkr[l]) * N_TOT + bc[l]);
    };
    auto sts = [&](int buf) {
        float* pa = sA + buf * TMG * APAD;
        float* pb = sB + buf * 16 * BPAD;
        #pragma unroll
        for (int l = 0; l < 4; l++) {
            *(float2*)(pa + sa[l])     = make_float2(__uint_as_float(f2tf32(ra[l].x)), __uint_as_float(f2tf32(ra[l].y)));
            *(float2*)(pa + sa[l] + 2) = make_float2(__uint_as_float(f2tf32(ra[l].z)), __uint_as_float(f2tf32(ra[l].w)));
        }
        #pragma unroll
        for (int l = 0; l < 2; l++) {
            float4 tv = make_float4(__uint_as_float(f2tf32(rb[l].x)), __uint_as_float(f2tf32(rb[l].y)),
                                    __uint_as_float(f2tf32(rb[l].z)), __uint_as_float(f2tf32(rb[l].w)));
            *(float4*)(pb + sb[l]) = tv;
        }
    };

    gload(0);
    sts(0);
    __syncthreads();

    #pragma unroll 1
    for (int kb = 0; kb < DM / 16; kb++) {
        const int buf = kb & 1;
        if (kb < DM / 16 - 1) gload((kb + 1) * 16);

        const float* pa = sA + buf * TMG * APAD + (wrow * 64 + g) * APAD + t;
        const float* pb = sB + buf * 16 * BPAD + t * BPAD + wcol * 64 + g;

        #pragma unroll
        for (int kt = 0; kt < 2; kt++) {
            uint32_t af[4][4];
            #pragma unroll
            for (int mt = 0; mt < 4; mt++) {
                const float* p = pa + mt * 16 * APAD + kt * 8;
                af[mt][0] = __float_as_uint(p[0]);
                af[mt][1] = __float_as_uint(p[8 * APAD]);
                af[mt][2] = __float_as_uint(p[4]);
                af[mt][3] = __float_as_uint(p[8 * APAD + 4]);
            }
            uint32_t bf[8][2];
            #pragma unroll
            for (int nt = 0; nt < 8; nt++) {
                const float* q = pb + kt * 8 * BPAD + nt * 8;
                bf[nt][0] = __float_as_uint(q[0]);
                bf[nt][1] = __float_as_uint(q[4 * BPAD]);
            }
            #pragma unroll
            for (int mt = 0; mt < 4; mt++)
                #pragma unroll
                for (int nt = 0; nt < 8; nt++)
                    mma8(acc[mt][nt], af[mt], bf[nt]);
        }

        if (kb < DM / 16 - 1) sts(buf ^ 1);
        __syncthreads();
    }

    // Epilogue: bias + scatter to Q/K/V
    #pragma unroll
    for (int mt = 0; mt < 4; mt++) {
        #pragma unroll
        for (int nt = 0; nt < 8; nt++) {
            int n0 = bn * TNG + wcol * 64 + nt * 8 + 2 * t;
            float bx = __ldg(&bias[n0]), by = __ldg(&bias[n0 + 1]);
            int h = n0 / 192;
            int r = n0 - h * 192;
            float* dst = (r < 64) ? g_Q : ((r < 128) ? g_K : g_V);
            #pragma unroll
            for (int half = 0; half < 2; half++) {
                int m  = bm * TMG + wrow * 64 + mt * 16 + g + half * 8;
                int b_ = m >> 11;
                int s_ = m & 2047;
                size_t o = ((((size_t)b_ * NH + h) * SEQ) + s_) * HD + (r & 63);
                *(float2*)(dst + o) = make_float2(acc[mt][nt][half * 2] + bx,
                                                  acc[mt][nt][half * 2 + 1] + by);
            }
        }
    }
}

// ---------------------------------------------------------------------------
// Kernel 2: causal flash attention on tensor cores (mma.sync tf32),
// with register prefetch of the next K/V tile to hide LDG latency.
// ---------------------------------------------------------------------------
#define QP 68
#define VP 72
#define L2E 1.44269504f

__global__ __launch_bounds__(256, 1) void attn_mma(float* __restrict__ out)
{
    extern __shared__ float sm[];
    float* Ps = sm;                    // [128][QP]  (Q tile, then P tiles)
    float* Ks = sm + 128 * QP;         // [64][QP]
    float* Vs = Ks + 64 * QP;          // [64][VP]

    const int tid  = threadIdx.x;
    const int wid  = tid >> 5;
    const int lane = tid & 31;
    const int g = lane >> 2, t = lane & 3;
    const int qt = gridDim.x - 1 - blockIdx.x;   // big-work CTAs first
    const int h = blockIdx.y, b = blockIdx.z;
    const int wb = wid * 16;
    const int row0 = qt * 128 + wb + g;

    const size_t head_base = (((size_t)b * NH + h) * SEQ) * HD;

    // Stage Q tile (x0.125, tf32) into Ps
    {
        const float* qsrc = g_Q + head_base + (size_t)qt * 128 * HD;
        #pragma unroll
        for (int i = 0; i < 8; i++) {
            int idx = tid + i * 256;
            int r = idx >> 4, c = (idx & 15) * 4;
            float4 v = *(const float4*)(qsrc + r * HD + c);
            float4 o;
            o.x = __uint_as_float(f2tf32(v.x * 0.125f));
            o.y = __uint_as_float(f2tf32(v.y * 0.125f));
            o.z = __uint_as_float(f2tf32(v.z * 0.125f));
            o.w = __uint_as_float(f2tf32(v.w * 0.125f));
            *(float4*)(Ps + r * QP + c) = o;
        }
    }
    __syncthreads();

    // Q A-fragments
    uint32_t aq[8][4];
    {
        const float* p = Ps + (wb + g) * QP + t;
        #pragma unroll
        for (int kt = 0; kt < 8; kt++) {
            aq[kt][0] = __float_as_uint(p[kt * 8]);
            aq[kt][1] = __float_as_uint(p[8 * QP + kt * 8]);
            aq[kt][2] = __float_as_uint(p[kt * 8 + 4]);
            aq[kt][3] = __float_as_uint(p[8 * QP + kt * 8 + 4]);
        }
    }

    float o[8][4];
    #pragma unroll
    for (int nt = 0; nt < 8; nt++)
        #pragma unroll
        for (int e = 0; e < 4; e++) o[nt][e] = 0.f;
    float m0 = -1e30f, m1 = -1e30f, l0 = 0.f, l1 = 0.f;

    const int nkb = qt * 2 + 2;
    const float* kbase = g_K + head_base;
    const float* vbase = g_V + head_base;

    // prefetch mapping: 4 f4 per thread per tensor
    int kvr[4], kvc[4];
    #pragma unroll
    for (int i = 0; i < 4; i++) {
        int idx = tid + i * 256;
        kvr[i] = idx >> 4;
        kvc[i] = (idx & 15) * 4;
    }
    float4 rk[4], rv[4];
    auto gload = [&](int kb) {
        const float* ksrc = kbase + (size_t)kb * 64 * HD;
        const float* vsrc = vbase + (size_t)kb * 64 * HD;
        #pragma unroll
        for (int i = 0; i < 4; i++) {
            rk[i] = *(const float4*)(ksrc + kvr[i] * HD + kvc[i]);
            rv[i] = *(const float4*)(vsrc + kvr[i] * HD + kvc[i]);
        }
    };
    auto sts_kv = [&]() {
        #pragma unroll
        for (int i = 0; i < 4; i++) {
            float4 ko, vo;
            ko.x = __uint_as_float(f2tf32(rk[i].x)); ko.y = __uint_as_float(f2tf32(rk[i].y));
            ko.z = __uint_as_float(f2tf32(rk[i].z)); ko.w = __uint_as_float(f2tf32(rk[i].w));
            vo.x = __uint_as_float(f2tf32(rv[i].x)); vo.y = __uint_as_float(f2tf32(rv[i].y));
            vo.z = __uint_as_float(f2tf32(rv[i].z)); vo.w = __uint_as_float(f2tf32(rv[i].w));
            *(float4*)(Ks + kvr[i] * QP + kvc[i]) = ko;
            *(float4*)(Vs + kvr[i] * VP + kvc[i]) = vo;
        }
    };

    gload(0);
    sts_kv();
    __syncthreads();

    #pragma unroll 1
    for (int kb = 0; kb < nkb; kb++) {
        if (kb + 1 < nkb) gload(kb + 1);

        if (kb * 64 <= qt * 128 + wb + 15) {
            // ---- QK^T ----
            float s[8][4];
            #pragma unroll
            for (int nt = 0; nt < 8; nt++)
                #pragma unroll
                for (int e = 0; e < 4; e++) s[nt][e] = 0.f;

            #pragma unroll
            for (int kt = 0; kt < 8; kt++) {
                #pragma unroll
                for (int nt = 0; nt < 8; nt++) {
                    uint32_t bk[2];
                    const float* kp = Ks + (nt * 8 + g) * QP + kt * 8 + t;
                    bk[0] = __float_as_uint(kp[0]);
                    bk[1] = __float_as_uint(kp[4]);
                    mma8(s[nt], aq[kt], bk);
                }
            }

            // causal mask near diagonal
            if (kb * 64 + 63 > qt * 128 + wb) {
                #pragma unroll
                for (int nt = 0; nt < 8; nt++) {
                    int col = kb * 64 + nt * 8 + 2 * t;
                    if (col     > row0)     s[nt][0] = -1e30f;
                    if (col + 1 > row0)     s[nt][1] = -1e30f;
                    if (col     > row0 + 8) s[nt][2] = -1e30f;
                    if (col + 1 > row0 + 8) s[nt][3] = -1e30f;
                }
            }

            // ---- online softmax ----
            float mb0 = -1e30f, mb1 = -1e30f;
            #pragma unroll
            for (int nt = 0; nt < 8; nt++) {
                mb0 = fmaxf(mb0, fmaxf(s[nt][0], s[nt][1]));
                mb1 = fmaxf(mb1, fmaxf(s[nt][2], s[nt][3]));
            }
            mb0 = fmaxf(mb0, __shfl_xor_sync(0xffffffffu, mb0, 1));
            mb0 = fmaxf(mb0, __shfl_xor_sync(0xffffffffu, mb0, 2));
            mb1 = fmaxf(mb1, __shfl_xor_sync(0xffffffffu, mb1, 1));
            mb1 = fmaxf(mb1, __shfl_xor_sync(0xffffffffu, mb1, 2));

            float mn0 = fmaxf(m0, mb0), mn1 = fmaxf(m1, mb1);
            float corr0 = exp2f((m0 - mn0) * L2E);
            float corr1 = exp2f((m1 - mn1) * L2E);

            float ls0 = 0.f, ls1 = 0.f;
            float* pw0 = Ps + (wb + g) * QP + 2 * t;
            float* pw1 = Ps + (wb + g + 8) * QP + 2 * t;
            #pragma unroll
            for (int nt = 0; nt < 8; nt++) {
                float p0 = exp2f((s[nt][0] - mn0) * L2E);
                float p1 = exp2f((s[nt][1] - mn0) * L2E);
                float p2 = exp2f((s[nt][2] - mn1) * L2E);
                float p3 = exp2f((s[nt][3] - mn1) * L2E);
                ls0 += p0 + p1;
                ls1 += p2 + p3;
                *(float2*)(pw0 + nt * 8) = make_float2(__uint_as_float(f2tf32(p0)),
                                                       __uint_as_float(f2tf32(p1)));
                *(float2*)(pw1 + nt * 8) = make_float2(__uint_as_float(f2tf32(p2)),
                                                       __uint_as_float(f2tf32(p3)));
            }
            ls0 += __shfl_xor_sync(0xffffffffu, ls0, 1);
            ls0 += __shfl_xor_sync(0xffffffffu, ls0, 2);
            ls1 += __shfl_xor_sync(0xffffffffu, ls1, 1);
            ls1 += __shfl_xor_sync(0xffffffffu, ls1, 2);
            l0 = l0 * corr0 + ls0;
            l1 = l1 * corr1 + ls1;
            m0 = mn0; m1 = mn1;

            #pragma unroll
            for (int nt = 0; nt < 8; nt++) {
                o[nt][0] *= corr0; o[nt][1] *= corr0;
                o[nt][2] *= corr1; o[nt][3] *= corr1;
            }

            __syncwarp();

            // ---- PV ----
            const float* pr = Ps + (wb + g) * QP + t;
            #pragma unroll
            for (int kt = 0; kt < 8; kt++) {
                uint32_t ap[4];
                ap[0] = __float_as_uint(pr[kt * 8]);
                ap[1] = __float_as_uint(pr[8 * QP + kt * 8]);
                ap[2] = __float_as_uint(pr[kt * 8 + 4]);
                ap[3] = __float_as_uint(pr[8 * QP + kt * 8 + 4]);
                #pragma unroll
                for (int nt = 0; nt < 8; nt++) {
                    uint32_t bv[2];
                    const float* vp = Vs + (kt * 8 + t) * VP + nt * 8 + g;
                    bv[0] = __float_as_uint(vp[0]);
                    bv[1] = __float_as_uint(vp[4 * VP]);
                    mma8(o[nt], ap, bv);
                }
            }
        }

        __syncthreads();                 // all Ks/Vs reads complete
        if (kb + 1 < nkb) {
            sts_kv();
            __syncthreads();
        }
    }

    // ---- write out ----
    const float inv0 = 1.f / l0, inv1 = 1.f / l1;
    float* op0 = out + ((size_t)b * SEQ + row0) * DM + h * HD + 2 * t;
    float* op1 = out + ((size_t)b * SEQ + row0 + 8) * DM + h * HD + 2 * t;
    #pragma unroll
    for (int nt = 0; nt < 8; nt++) {
        *(float2*)(op0 + nt * 8) = make_float2(o[nt][0] * inv0, o[nt][1] * inv0);
        *(float2*)(op1 + nt * 8) = make_float2(o[nt][2] * inv1, o[nt][3] * inv1);
    }
}

// ---------------------------------------------------------------------------
extern "C" void kernel_launch(void* const* d_in, const int* in_sizes, int n_in,
                              void* d_out, int out_size)
{
    (void)in_sizes; (void)n_in; (void)out_size;
    const float* x    = (const float*)d_in[0];   // [B, S, D]
    const float* Wqkv = (const float*)d_in[1];   // [D, 3D]
    const float* bqkv = (const float*)d_in[2];   // [3D]
    float* out = (float*)d_out;                  // [B, S, D]

    const int gemm_smem = (2 * TMG * APAD + 2 * 16 * BPAD) * 4;  // 58368 B
    cudaFuncSetAttribute(qkv_gemm_mma, cudaFuncAttributeMaxDynamicSharedMemorySize, gemm_smem);
    dim3 ggrid(N_TOT / TNG, M_TOT / TMG);        // (24, 32)
    qkv_gemm_mma<<<ggrid, 256, gemm_smem>>>(x, Wqkv, bqkv);

    const int attn_smem = (128 * QP + 64 * QP + 64 * VP) * 4;    // 70656 B
    cudaFuncSetAttribute(attn_mma, cudaFuncAttributeMaxDynamicSharedMemorySize, attn_smem);
    dim3 agrid(SEQ / 128, NH, BZ);               // (16, 16, 4)
    attn_mma<<<agrid, 256, attn_smem>>>(out);
}

// round 6
// speedup vs baseline: 3.6520x; 1.0111x over previous
#include <cuda_runtime.h>
#include <cstdint>

// Problem constants
#define BZ 4
#define SEQ 2048
#define DM 1024
#define NH 16
#define HD 64
#define M_TOT (BZ*SEQ)        // 8192
#define N_TOT (3*DM)          // 3072

// Scratch
__device__ float g_Q[BZ*NH*SEQ*HD];
__device__ float g_K[BZ*NH*SEQ*HD];
__device__ float g_V[BZ*NH*SEQ*HD];
__device__ float g_Xc[M_TOT*DM];     // tf32-rounded x
__device__ float g_Wc[DM*N_TOT];     // tf32-rounded W

// ---------------------------------------------------------------------------
// helpers
// ---------------------------------------------------------------------------
__device__ __forceinline__ uint32_t f2tf32(float f){
    uint32_t u; asm("cvt.rna.tf32.f32 %0, %1;" : "=r"(u) : "f"(f)); return u;
}
__device__ __forceinline__ float rna(float f){ return __uint_as_float(f2tf32(f)); }
__device__ __forceinline__ void mma8(float* c, const uint32_t* a, const uint32_t* b){
    asm volatile("mma.sync.aligned.m16n8k8.row.col.f32.tf32.tf32.f32 "
        "{%0,%1,%2,%3}, {%4,%5,%6,%7}, {%8,%9}, {%0,%1,%2,%3};"
        : "+f"(c[0]), "+f"(c[1]), "+f"(c[2]), "+f"(c[3])
        : "r"(a[0]), "r"(a[1]), "r"(a[2]), "r"(a[3]), "r"(b[0]), "r"(b[1]));
}
__device__ __forceinline__ uint32_t smem_u32(const void* p){
    uint32_t a;
    asm("{ .reg .u64 t; cvta.to.shared.u64 t, %1; cvt.u32.u64 %0, t; }" : "=r"(a) : "l"(p));
    return a;
}
__device__ __forceinline__ void cp16(uint32_t dst, const void* src){
    asm volatile("cp.async.cg.shared.global [%0], [%1], 16;" :: "r"(dst), "l"(src));
}
#define CP_COMMIT() asm volatile("cp.async.commit_group;" ::: "memory")
#define CP_WAIT(n)  asm volatile("cp.async.wait_group %0;" :: "n"(n) : "memory")

// ---------------------------------------------------------------------------
// Kernel 0: prepass — tf32-round x and W into scratch.
// ---------------------------------------------------------------------------
__global__ __launch_bounds__(256) void cvt_prepass(const float* __restrict__ x,
                                                   const float* __restrict__ W)
{
    const size_t NX = (size_t)M_TOT * DM / 4;     // f4 count for x
    const size_t NW = (size_t)DM * N_TOT / 4;
    size_t i = (size_t)blockIdx.x * blockDim.x + threadIdx.x;
    size_t stride = (size_t)gridDim.x * blockDim.x;
    for (size_t k = i; k < NX; k += stride) {
        float4 v = ((const float4*)x)[k];
        v.x = rna(v.x); v.y = rna(v.y); v.z = rna(v.z); v.w = rna(v.w);
        ((float4*)g_Xc)[k] = v;
    }
    for (size_t k = i; k < NW; k += stride) {
        float4 v = ((const float4*)W)[k];
        v.x = rna(v.x); v.y = rna(v.y); v.z = rna(v.z); v.w = rna(v.w);
        ((float4*)g_Wc)[k] = v;
    }
}

// ---------------------------------------------------------------------------
// Kernel 1: QKV GEMM via mma.sync tf32, cp.async 3-stage pipeline.
// CTA tile 256(M) x 128(N), BK=16, 8 warps as 4M x 2N, warp tile 64x64.
// Inputs pre-converted (g_Xc/g_Wc). Epilogue writes RNA'd Q(x0.125)/K/V.
// ---------------------------------------------------------------------------
#define APAD 20
#define BPAD 136
#define TMG 256
#define TNG 128
#define STAGE_A (TMG*APAD)     // 5120 floats
#define STAGE_B (16*BPAD)      // 2176 floats

__global__ __launch_bounds__(256, 1) void qkv_gemm_mma(const float* __restrict__ bias)
{
    extern __shared__ float smg[];
    float* sA = smg;                        // [3][STAGE_A]
    float* sB = smg + 3 * STAGE_A;          // [3][STAGE_B]
    const uint32_t uA = smem_u32(sA);
    const uint32_t uB = smem_u32(sB);

    const int tid  = threadIdx.x;
    const int wid  = tid >> 5;
    const int lane = tid & 31;
    const int g = lane >> 2, t = lane & 3;
    const int wrow = wid & 3;
    const int wcol = wid >> 2;
    const int bm = blockIdx.y, bn = blockIdx.x;

    const float* Ablk = g_Xc + (size_t)(bm * TMG) * DM;
    const float* Wblk = g_Wc + bn * TNG;

    int ar[4], akc[4], sa[4];
    #pragma unroll
    for (int l = 0; l < 4; l++) {
        int idx = tid + l * 256;
        ar[l]  = idx >> 2;
        akc[l] = (idx & 3) * 4;
        sa[l]  = ar[l] * APAD + akc[l];
    }
    int bkr[2], bc[2], sb[2];
    #pragma unroll
    for (int l = 0; l < 2; l++) {
        int idx = tid + l * 256;
        bkr[l] = idx >> 5;
        bc[l]  = (idx & 31) * 4;
        sb[l]  = bkr[l] * BPAD + bc[l];
    }

    auto issue = [&](int slot, int k0) {
        uint32_t pa = uA + (slot * STAGE_A) * 4;
        uint32_t pb = uB + (slot * STAGE_B) * 4;
        #pragma unroll
        for (int l = 0; l < 4; l++)
            cp16(pa + sa[l] * 4, Ablk + (size_t)ar[l] * DM + k0 + akc[l]);
        #pragma unroll
        for (int l = 0; l < 2; l++)
            cp16(pb + sb[l] * 4, Wblk + (size_t)(k0 + bkr[l]) * N_TOT + bc[l]);
    };

    float acc[4][8][4];
    #pragma unroll
    for (int mt = 0; mt < 4; mt++)
        #pragma unroll
        for (int nt = 0; nt < 8; nt++)
            #pragma unroll
            for (int e = 0; e < 4; e++) acc[mt][nt][e] = 0.f;

    issue(0, 0);  CP_COMMIT();
    issue(1, 16); CP_COMMIT();
    CP_WAIT(1);
    __syncthreads();

    int slot = 0;
    #pragma unroll 1
    for (int kb = 0; kb < DM / 16; kb++) {
        if (kb + 2 < DM / 16) {
            int ns = slot + 2; if (ns >= 3) ns -= 3;
            issue(ns, (kb + 2) * 16);
            CP_COMMIT();
        }

        const float* pa = sA + slot * STAGE_A + (wrow * 64 + g) * APAD + t;
        const float* pb = sB + slot * STAGE_B + t * BPAD + wcol * 64 + g;

        #pragma unroll
        for (int kt = 0; kt < 2; kt++) {
            uint32_t af[4][4];
            #pragma unroll
            for (int mt = 0; mt < 4; mt++) {
                const float* p = pa + mt * 16 * APAD + kt * 8;
                af[mt][0] = __float_as_uint(p[0]);
                af[mt][1] = __float_as_uint(p[8 * APAD]);
                af[mt][2] = __float_as_uint(p[4]);
                af[mt][3] = __float_as_uint(p[8 * APAD + 4]);
            }
            uint32_t bf[8][2];
            #pragma unroll
            for (int nt = 0; nt < 8; nt++) {
                const float* q = pb + kt * 8 * BPAD + nt * 8;
                bf[nt][0] = __float_as_uint(q[0]);
                bf[nt][1] = __float_as_uint(q[4 * BPAD]);
            }
            #pragma unroll
            for (int mt = 0; mt < 4; mt++)
                #pragma unroll
                for (int nt = 0; nt < 8; nt++)
                    mma8(acc[mt][nt], af[mt], bf[nt]);
        }

        if (kb + 2 < DM / 16) { CP_WAIT(1); } else { CP_WAIT(0); }
        __syncthreads();
        if (++slot == 3) slot = 0;
    }

    // Epilogue: bias + RNA (+ Q scale) + scatter to Q/K/V
    #pragma unroll
    for (int mt = 0; mt < 4; mt++) {
        #pragma unroll
        for (int nt = 0; nt < 8; nt++) {
            int n0 = bn * TNG + wcol * 64 + nt * 8 + 2 * t;
            float bx = __ldg(&bias[n0]), by = __ldg(&bias[n0 + 1]);
            int h = n0 / 192;
            int r = n0 - h * 192;
            float* dst = (r < 64) ? g_Q : ((r < 128) ? g_K : g_V);
            float scl = (r < 64) ? 0.125f : 1.f;
            #pragma unroll
            for (int half = 0; half < 2; half++) {
                int m  = bm * TMG + wrow * 64 + mt * 16 + g + half * 8;
                int b_ = m >> 11;
                int s_ = m & 2047;
                size_t o = ((((size_t)b_ * NH + h) * SEQ) + s_) * HD + (r & 63);
                *(float2*)(dst + o) = make_float2(rna((acc[mt][nt][half * 2]     + bx) * scl),
                                                  rna((acc[mt][nt][half * 2 + 1] + by) * scl));
            }
        }
    }
}

// ---------------------------------------------------------------------------
// Kernel 2: causal flash attention on tensor cores (mma.sync tf32),
// cp.async double-buffered K/V tiles (inputs pre-rounded, no converts).
// ---------------------------------------------------------------------------
#define QP 68
#define VP 72
#define L2E 1.44269504f

__global__ __launch_bounds__(256, 1) void attn_mma(float* __restrict__ out)
{
    extern __shared__ float sm[];
    float* Ps = sm;                     // [128][QP]
    float* Ks = sm + 128 * QP;          // [2][64][QP]
    float* Vs = Ks + 2 * 64 * QP;       // [2][64][VP]
    const uint32_t uK = smem_u32(Ks);
    const uint32_t uV = smem_u32(Vs);

    const int tid  = threadIdx.x;
    const int wid  = tid >> 5;
    const int lane = tid & 31;
    const int g = lane >> 2, t = lane & 3;
    const int qt = gridDim.x - 1 - blockIdx.x;   // big-work CTAs first
    const int h = blockIdx.y, b = blockIdx.z;
    const int wb = wid * 16;
    const int row0 = qt * 128 + wb + g;

    const size_t head_base = (((size_t)b * NH + h) * SEQ) * HD;
    const float* kbase = g_K + head_base;
    const float* vbase = g_V + head_base;
    const int nkb = qt * 2 + 2;

    // K/V cp.async mapping: 4 f4 per thread per tensor
    int kvr[4], kvc[4];
    #pragma unroll
    for (int i = 0; i < 4; i++) {
        int idx = tid + i * 256;
        kvr[i] = idx >> 4;
        kvc[i] = (idx & 15) * 4;
    }
    auto issueKV = [&](int kb, int slot) {
        const float* ksrc = kbase + (size_t)kb * 64 * HD;
        const float* vsrc = vbase + (size_t)kb * 64 * HD;
        uint32_t kd = uK + (slot * 64 * QP) * 4;
        uint32_t vd = uV + (slot * 64 * VP) * 4;
        #pragma unroll
        for (int i = 0; i < 4; i++) {
            cp16(kd + (kvr[i] * QP + kvc[i]) * 4, ksrc + kvr[i] * HD + kvc[i]);
            cp16(vd + (kvr[i] * VP + kvc[i]) * 4, vsrc + kvr[i] * HD + kvc[i]);
        }
    };

    issueKV(0, 0);
    CP_COMMIT();

    // Stage Q tile (already scaled+rounded) into Ps
    {
        const float* qsrc = g_Q + head_base + (size_t)qt * 128 * HD;
        #pragma unroll
        for (int i = 0; i < 8; i++) {
            int idx = tid + i * 256;
            int r = idx >> 4, c = (idx & 15) * 4;
            *(float4*)(Ps + r * QP + c) = *(const float4*)(qsrc + r * HD + c);
        }
    }
    CP_WAIT(0);
    __syncthreads();

    // Q A-fragments
    uint32_t aq[8][4];
    {
        const float* p = Ps + (wb + g) * QP + t;
        #pragma unroll
        for (int kt = 0; kt < 8; kt++) {
            aq[kt][0] = __float_as_uint(p[kt * 8]);
            aq[kt][1] = __float_as_uint(p[8 * QP + kt * 8]);
            aq[kt][2] = __float_as_uint(p[kt * 8 + 4]);
            aq[kt][3] = __float_as_uint(p[8 * QP + kt * 8 + 4]);
        }
    }

    float o[8][4];
    #pragma unroll
    for (int nt = 0; nt < 8; nt++)
        #pragma unroll
        for (int e = 0; e < 4; e++) o[nt][e] = 0.f;
    float m0 = -1e30f, m1 = -1e30f, l0 = 0.f, l1 = 0.f;

    #pragma unroll 1
    for (int kb = 0; kb < nkb; kb++) {
        const int slot = kb & 1;
        if (kb + 1 < nkb) {
            issueKV(kb + 1, slot ^ 1);
            CP_COMMIT();
        }

        if (kb * 64 <= qt * 128 + wb + 15) {
            const float* Kslot = Ks + slot * 64 * QP;
            const float* Vslot = Vs + slot * 64 * VP;

            // ---- QK^T ----
            float s[8][4];
            #pragma unroll
            for (int nt = 0; nt < 8; nt++)
                #pragma unroll
                for (int e = 0; e < 4; e++) s[nt][e] = 0.f;

            #pragma unroll
            for (int kt = 0; kt < 8; kt++) {
                #pragma unroll
                for (int nt = 0; nt < 8; nt++) {
                    uint32_t bk[2];
                    const float* kp = Kslot + (nt * 8 + g) * QP + kt * 8 + t;
                    bk[0] = __float_as_uint(kp[0]);
                    bk[1] = __float_as_uint(kp[4]);
                    mma8(s[nt], aq[kt], bk);
                }
            }

            // causal mask near diagonal
            if (kb * 64 + 63 > qt * 128 + wb) {
                #pragma unroll
                for (int nt = 0; nt < 8; nt++) {
                    int col = kb * 64 + nt * 8 + 2 * t;
                    if (col     > row0)     s[nt][0] = -1e30f;
                    if (col + 1 > row0)     s[nt][1] = -1e30f;
                    if (col     > row0 + 8) s[nt][2] = -1e30f;
                    if (col + 1 > row0 + 8) s[nt][3] = -1e30f;
                }
            }

            // ---- online softmax ----
            float mb0 = -1e30f, mb1 = -1e30f;
            #pragma unroll
            for (int nt = 0; nt < 8; nt++) {
                mb0 = fmaxf(mb0, fmaxf(s[nt][0], s[nt][1]));
                mb1 = fmaxf(mb1, fmaxf(s[nt][2], s[nt][3]));
            }
            mb0 = fmaxf(mb0, __shfl_xor_sync(0xffffffffu, mb0, 1));
            mb0 = fmaxf(mb0, __shfl_xor_sync(0xffffffffu, mb0, 2));
            mb1 = fmaxf(mb1, __shfl_xor_sync(0xffffffffu, mb1, 1));
            mb1 = fmaxf(mb1, __shfl_xor_sync(0xffffffffu, mb1, 2));

            float mn0 = fmaxf(m0, mb0), mn1 = fmaxf(m1, mb1);
            float corr0 = exp2f((m0 - mn0) * L2E);
            float corr1 = exp2f((m1 - mn1) * L2E);

            float ls0 = 0.f, ls1 = 0.f;
            float* pw0 = Ps + (wb + g) * QP + 2 * t;
            float* pw1 = Ps + (wb + g + 8) * QP + 2 * t;
            #pragma unroll
            for (int nt = 0; nt < 8; nt++) {
                float p0 = exp2f((s[nt][0] - mn0) * L2E);
                float p1 = exp2f((s[nt][1] - mn0) * L2E);
                float p2 = exp2f((s[nt][2] - mn1) * L2E);
                float p3 = exp2f((s[nt][3] - mn1) * L2E);
                ls0 += p0 + p1;
                ls1 += p2 + p3;
                *(float2*)(pw0 + nt * 8) = make_float2(__uint_as_float(f2tf32(p0)),
                                                       __uint_as_float(f2tf32(p1)));
                *(float2*)(pw1 + nt * 8) = make_float2(__uint_as_float(f2tf32(p2)),
                                                       __uint_as_float(f2tf32(p3)));
            }
            ls0 += __shfl_xor_sync(0xffffffffu, ls0, 1);
            ls0 += __shfl_xor_sync(0xffffffffu, ls0, 2);
            ls1 += __shfl_xor_sync(0xffffffffu, ls1, 1);
            ls1 += __shfl_xor_sync(0xffffffffu, ls1, 2);
            l0 = l0 * corr0 + ls0;
            l1 = l1 * corr1 + ls1;
            m0 = mn0; m1 = mn1;

            #pragma unroll
            for (int nt = 0; nt < 8; nt++) {
                o[nt][0] *= corr0; o[nt][1] *= corr0;
                o[nt][2] *= corr1; o[nt][3] *= corr1;
            }

            __syncwarp();

            // ---- PV ----
            const float* pr = Ps + (wb + g) * QP + t;
            #pragma unroll
            for (int kt = 0; kt < 8; kt++) {
                uint32_t ap[4];
                ap[0] = __float_as_uint(pr[kt * 8]);
                ap[1] = __float_as_uint(pr[8 * QP + kt * 8]);
                ap[2] = __float_as_uint(pr[kt * 8 + 4]);
                ap[3] = __float_as_uint(pr[8 * QP + kt * 8 + 4]);
                #pragma unroll
                for (int nt = 0; nt < 8; nt++) {
                    uint32_t bv[2];
                    const float* vp = Vslot + (kt * 8 + t) * VP + nt * 8 + g;
                    bv[0] = __float_as_uint(vp[0]);
                    bv[1] = __float_as_uint(vp[4 * VP]);
                    mma8(o[nt], ap, bv);
                }
            }
            __syncwarp();
        }

        CP_WAIT(0);          // next K/V tile arrived
        __syncthreads();     // all warps done with current slot
    }

    // ---- write out ----
    const float inv0 = 1.f / l0, inv1 = 1.f / l1;
    float* op0 = out + ((size_t)b * SEQ + row0) * DM + h * HD + 2 * t;
    float* op1 = out + ((size_t)b * SEQ + row0 + 8) * DM + h * HD + 2 * t;
    #pragma unroll
    for (int nt = 0; nt < 8; nt++) {
        *(float2*)(op0 + nt * 8) = make_float2(o[nt][0] * inv0, o[nt][1] * inv0);
        *(float2*)(op1 + nt * 8) = make_float2(o[nt][2] * inv1, o[nt][3] * inv1);
    }
}

// ---------------------------------------------------------------------------
extern "C" void kernel_launch(void* const* d_in, const int* in_sizes, int n_in,
                              void* d_out, int out_size)
{
    (void)in_sizes; (void)n_in; (void)out_size;
    const float* x    = (const float*)d_in[0];   // [B, S, D]
    const float* Wqkv = (const float*)d_in[1];   // [D, 3D]
    const float* bqkv = (const float*)d_in[2];   // [3D]
    float* out = (float*)d_out;                  // [B, S, D]

    cvt_prepass<<<1184, 256>>>(x, Wqkv);

    const int gemm_smem = (3 * STAGE_A + 3 * STAGE_B) * 4;       // 87552 B
    cudaFuncSetAttribute(qkv_gemm_mma, cudaFuncAttributeMaxDynamicSharedMemorySize, gemm_smem);
    dim3 ggrid(N_TOT / TNG, M_TOT / TMG);        // (24, 32)
    qkv_gemm_mma<<<ggrid, 256, gemm_smem>>>(bqkv);

    const int attn_smem = (128 * QP + 2 * 64 * QP + 2 * 64 * VP) * 4;  // 106496 B
    cudaFuncSetAttribute(attn_mma, cudaFuncAttributeMaxDynamicSharedMemorySize, attn_smem);
    dim3 agrid(SEQ / 128, NH, BZ);               // (16, 16, 4)
    attn_mma<<<agrid, 256, attn_smem>>>(out);
}

// round 7
// speedup vs baseline: 3.7118x; 1.0164x over previous
#include <cuda_runtime.h>
#include <cstdint>

// Problem constants
#define BZ 4
#define SEQ 2048
#define DM 1024
#define NH 16
#define HD 64
#define M_TOT (BZ*SEQ)        // 8192
#define N_TOT (3*DM)          // 3072

// Scratch
__device__ float g_Q[BZ*NH*SEQ*HD];
__device__ float g_K[BZ*NH*SEQ*HD];
__device__ float g_V[BZ*NH*SEQ*HD];
__device__ float g_Xc[M_TOT*DM];     // tf32-rounded x
__device__ float g_Wc[DM*N_TOT];     // tf32-rounded W

// ---------------------------------------------------------------------------
// helpers
// ---------------------------------------------------------------------------
__device__ __forceinline__ uint32_t f2tf32(float f){
    uint32_t u; asm("cvt.rna.tf32.f32 %0, %1;" : "=r"(u) : "f"(f)); return u;
}
__device__ __forceinline__ float rna(float f){ return __uint_as_float(f2tf32(f)); }
__device__ __forceinline__ void mma8(float* c, const uint32_t* a, const uint32_t* b){
    asm volatile("mma.sync.aligned.m16n8k8.row.col.f32.tf32.tf32.f32 "
        "{%0,%1,%2,%3}, {%4,%5,%6,%7}, {%8,%9}, {%0,%1,%2,%3};"
        : "+f"(c[0]), "+f"(c[1]), "+f"(c[2]), "+f"(c[3])
        : "r"(a[0]), "r"(a[1]), "r"(a[2]), "r"(a[3]), "r"(b[0]), "r"(b[1]));
}
__device__ __forceinline__ uint32_t smem_u32(const void* p){
    uint32_t a;
    asm("{ .reg .u64 t; cvta.to.shared.u64 t, %1; cvt.u32.u64 %0, t; }" : "=r"(a) : "l"(p));
    return a;
}
__device__ __forceinline__ void cp16(uint32_t dst, const void* src){
    asm volatile("cp.async.cg.shared.global [%0], [%1], 16;" :: "r"(dst), "l"(src));
}
#define CP_COMMIT() asm volatile("cp.async.commit_group;" ::: "memory")
#define CP_WAIT(n)  asm volatile("cp.async.wait_group %0;" :: "n"(n) : "memory")

// ---------------------------------------------------------------------------
// Kernel 0: prepass — tf32-round x and W into scratch.
// ---------------------------------------------------------------------------
__global__ __launch_bounds__(256) void cvt_prepass(const float* __restrict__ x,
                                                   const float* __restrict__ W)
{
    const size_t NX = (size_t)M_TOT * DM / 4;
    const size_t NW = (size_t)DM * N_TOT / 4;
    size_t i = (size_t)blockIdx.x * blockDim.x + threadIdx.x;
    size_t stride = (size_t)gridDim.x * blockDim.x;
    for (size_t k = i; k < NX; k += stride) {
        float4 v = ((const float4*)x)[k];
        v.x = rna(v.x); v.y = rna(v.y); v.z = rna(v.z); v.w = rna(v.w);
        ((float4*)g_Xc)[k] = v;
    }
    for (size_t k = i; k < NW; k += stride) {
        float4 v = ((const float4*)W)[k];
        v.x = rna(v.x); v.y = rna(v.y); v.z = rna(v.z); v.w = rna(v.w);
        ((float4*)g_Wc)[k] = v;
    }
}

// ---------------------------------------------------------------------------
// Kernel 1: QKV GEMM via mma.sync tf32, cp.async 3-stage pipeline (unchanged).
// ---------------------------------------------------------------------------
#define APAD 20
#define BPAD 136
#define TMG 256
#define TNG 128
#define STAGE_A (TMG*APAD)
#define STAGE_B (16*BPAD)

__global__ __launch_bounds__(256, 1) void qkv_gemm_mma(const float* __restrict__ bias)
{
    extern __shared__ float smg[];
    float* sA = smg;
    float* sB = smg + 3 * STAGE_A;
    const uint32_t uA = smem_u32(sA);
    const uint32_t uB = smem_u32(sB);

    const int tid  = threadIdx.x;
    const int wid  = tid >> 5;
    const int lane = tid & 31;
    const int g = lane >> 2, t = lane & 3;
    const int wrow = wid & 3;
    const int wcol = wid >> 2;
    const int bm = blockIdx.y, bn = blockIdx.x;

    const float* Ablk = g_Xc + (size_t)(bm * TMG) * DM;
    const float* Wblk = g_Wc + bn * TNG;

    int ar[4], akc[4], sa[4];
    #pragma unroll
    for (int l = 0; l < 4; l++) {
        int idx = tid + l * 256;
        ar[l]  = idx >> 2;
        akc[l] = (idx & 3) * 4;
        sa[l]  = ar[l] * APAD + akc[l];
    }
    int bkr[2], bc[2], sb[2];
    #pragma unroll
    for (int l = 0; l < 2; l++) {
        int idx = tid + l * 256;
        bkr[l] = idx >> 5;
        bc[l]  = (idx & 31) * 4;
        sb[l]  = bkr[l] * BPAD + bc[l];
    }

    auto issue = [&](int slot, int k0) {
        uint32_t pa = uA + (slot * STAGE_A) * 4;
        uint32_t pb = uB + (slot * STAGE_B) * 4;
        #pragma unroll
        for (int l = 0; l < 4; l++)
            cp16(pa + sa[l] * 4, Ablk + (size_t)ar[l] * DM + k0 + akc[l]);
        #pragma unroll
        for (int l = 0; l < 2; l++)
            cp16(pb + sb[l] * 4, Wblk + (size_t)(k0 + bkr[l]) * N_TOT + bc[l]);
    };

    float acc[4][8][4];
    #pragma unroll
    for (int mt = 0; mt < 4; mt++)
        #pragma unroll
        for (int nt = 0; nt < 8; nt++)
            #pragma unroll
            for (int e = 0; e < 4; e++) acc[mt][nt][e] = 0.f;

    issue(0, 0);  CP_COMMIT();
    issue(1, 16); CP_COMMIT();
    CP_WAIT(1);
    __syncthreads();

    int slot = 0;
    #pragma unroll 1
    for (int kb = 0; kb < DM / 16; kb++) {
        if (kb + 2 < DM / 16) {
            int ns = slot + 2; if (ns >= 3) ns -= 3;
            issue(ns, (kb + 2) * 16);
            CP_COMMIT();
        }

        const float* pa = sA + slot * STAGE_A + (wrow * 64 + g) * APAD + t;
        const float* pb = sB + slot * STAGE_B + t * BPAD + wcol * 64 + g;

        #pragma unroll
        for (int kt = 0; kt < 2; kt++) {
            uint32_t af[4][4];
            #pragma unroll
            for (int mt = 0; mt < 4; mt++) {
                const float* p = pa + mt * 16 * APAD + kt * 8;
                af[mt][0] = __float_as_uint(p[0]);
                af[mt][1] = __float_as_uint(p[8 * APAD]);
                af[mt][2] = __float_as_uint(p[4]);
                af[mt][3] = __float_as_uint(p[8 * APAD + 4]);
            }
            uint32_t bf[8][2];
            #pragma unroll
            for (int nt = 0; nt < 8; nt++) {
                const float* q = pb + kt * 8 * BPAD + nt * 8;
                bf[nt][0] = __float_as_uint(q[0]);
                bf[nt][1] = __float_as_uint(q[4 * BPAD]);
            }
            #pragma unroll
            for (int mt = 0; mt < 4; mt++)
                #pragma unroll
                for (int nt = 0; nt < 8; nt++)
                    mma8(acc[mt][nt], af[mt], bf[nt]);
        }

        if (kb + 2 < DM / 16) { CP_WAIT(1); } else { CP_WAIT(0); }
        __syncthreads();
        if (++slot == 3) slot = 0;
    }

    #pragma unroll
    for (int mt = 0; mt < 4; mt++) {
        #pragma unroll
        for (int nt = 0; nt < 8; nt++) {
            int n0 = bn * TNG + wcol * 64 + nt * 8 + 2 * t;
            float bx = __ldg(&bias[n0]), by = __ldg(&bias[n0 + 1]);
            int h = n0 / 192;
            int r = n0 - h * 192;
            float* dst = (r < 64) ? g_Q : ((r < 128) ? g_K : g_V);
            float scl = (r < 64) ? 0.125f : 1.f;
            #pragma unroll
            for (int half = 0; half < 2; half++) {
                int m  = bm * TMG + wrow * 64 + mt * 16 + g + half * 8;
                int b_ = m >> 11;
                int s_ = m & 2047;
                size_t o = ((((size_t)b_ * NH + h) * SEQ) + s_) * HD + (r & 63);
                *(float2*)(dst + o) = make_float2(rna((acc[mt][nt][half * 2]     + bx) * scl),
                                                  rna((acc[mt][nt][half * 2 + 1] + by) * scl));
            }
        }
    }
}

// ---------------------------------------------------------------------------
// Kernel 2: causal flash attention, mma.sync tf32.
// 8 warps x 32 q-rows = 256 q-rows per CTA. K/V fragments shared across the
// two 16-row m-tiles (mma:LDS ratio 0.8 vs 0.44 before).
// Single-buffered K/V with register prefetch issued after QK.
// ---------------------------------------------------------------------------
#define QP 68
#define VP 72
#define CTAQ 256
#define L2E 1.44269504f

__global__ __launch_bounds__(256, 1) void attn_mma(float* __restrict__ out)
{
    extern __shared__ float sm[];
    float* Ps = sm;                     // [256][QP]  (Q tile, then P tiles)
    float* Ks = sm + CTAQ * QP;         // [64][QP]
    float* Vs = Ks + 64 * QP;           // [64][VP]

    const int tid  = threadIdx.x;
    const int wid  = tid >> 5;
    const int lane = tid & 31;
    const int g = lane >> 2, t = lane & 3;
    const int qt = gridDim.x - 1 - blockIdx.x;   // big-work CTAs first
    const int h = blockIdx.y, b = blockIdx.z;
    const int wb = wid * 32;                     // warp q-row base in tile
    const int qbase = qt * CTAQ;
    const int row0 = qbase + wb + g;             // tile0 first row (tile1: +16)

    const size_t head_base = (((size_t)b * NH + h) * SEQ) * HD;
    const float* kbase = g_K + head_base;
    const float* vbase = g_V + head_base;
    const int nkb = qt * (CTAQ / 64) + (CTAQ / 64);

    // K/V prefetch mapping: 4 f4 per thread per tensor
    int kvr[4], kvc[4];
    #pragma unroll
    for (int i = 0; i < 4; i++) {
        int idx = tid + i * 256;
        kvr[i] = idx >> 4;
        kvc[i] = (idx & 15) * 4;
    }
    float4 rk[4], rv[4];
    auto gload = [&](int kb) {
        const float* ksrc = kbase + (size_t)kb * 64 * HD;
        const float* vsrc = vbase + (size_t)kb * 64 * HD;
        #pragma unroll
        for (int i = 0; i < 4; i++) {
            rk[i] = *(const float4*)(ksrc + kvr[i] * HD + kvc[i]);
            rv[i] = *(const float4*)(vsrc + kvr[i] * HD + kvc[i]);
        }
    };
    auto sts_kv = [&]() {
        #pragma unroll
        for (int i = 0; i < 4; i++) {
            *(float4*)(Ks + kvr[i] * QP + kvc[i]) = rk[i];
            *(float4*)(Vs + kvr[i] * VP + kvc[i]) = rv[i];
        }
    };

    gload(0);

    // Stage Q tile (pre-scaled, pre-rounded) into Ps: 4096 f4, 16/thread
    {
        const float* qsrc = g_Q + head_base + (size_t)qbase * HD;
        #pragma unroll
        for (int i = 0; i < 16; i++) {
            int idx = tid + i * 256;
            int r = idx >> 4, c = (idx & 15) * 4;
            *(float4*)(Ps + r * QP + c) = *(const float4*)(qsrc + r * HD + c);
        }
    }
    sts_kv();
    __syncthreads();

    // Q A-fragments for both 16-row tiles
    uint32_t aq0[8][4], aq1[8][4];
    {
        const float* p0 = Ps + (wb + g) * QP + t;
        const float* p1 = Ps + (wb + 16 + g) * QP + t;
        #pragma unroll
        for (int kt = 0; kt < 8; kt++) {
            aq0[kt][0] = __float_as_uint(p0[kt * 8]);
            aq0[kt][1] = __float_as_uint(p0[8 * QP + kt * 8]);
            aq0[kt][2] = __float_as_uint(p0[kt * 8 + 4]);
            aq0[kt][3] = __float_as_uint(p0[8 * QP + kt * 8 + 4]);
            aq1[kt][0] = __float_as_uint(p1[kt * 8]);
            aq1[kt][1] = __float_as_uint(p1[8 * QP + kt * 8]);
            aq1[kt][2] = __float_as_uint(p1[kt * 8 + 4]);
            aq1[kt][3] = __float_as_uint(p1[8 * QP + kt * 8 + 4]);
        }
    }

    float o0[8][4], o1[8][4];
    #pragma unroll
    for (int nt = 0; nt < 8; nt++)
        #pragma unroll
        for (int e = 0; e < 4; e++) { o0[nt][e] = 0.f; o1[nt][e] = 0.f; }
    float m00 = -1e30f, m01 = -1e30f, m10 = -1e30f, m11 = -1e30f;
    float l00 = 0.f, l01 = 0.f, l10 = 0.f, l11 = 0.f;

    #pragma unroll 1
    for (int kb = 0; kb < nkb; kb++) {
        const bool active = (kb * 64 <= qbase + wb + 31);

        if (active) {
            // ---- QK^T for both tiles, sharing K fragments ----
            float s0[8][4], s1[8][4];
            #pragma unroll
            for (int nt = 0; nt < 8; nt++)
                #pragma unroll
                for (int e = 0; e < 4; e++) { s0[nt][e] = 0.f; s1[nt][e] = 0.f; }

            #pragma unroll
            for (int kt = 0; kt < 8; kt++) {
                #pragma unroll
                for (int nt = 0; nt < 8; nt++) {
                    uint32_t bk[2];
                    const float* kp = Ks + (nt * 8 + g) * QP + kt * 8 + t;
                    bk[0] = __float_as_uint(kp[0]);
                    bk[1] = __float_as_uint(kp[4]);
                    mma8(s0[nt], aq0[kt], bk);
                    mma8(s1[nt], aq1[kt], bk);
                }
            }

            // prefetch next K/V now (hides LDG behind softmax+PV)
            if (kb + 1 < nkb) gload(kb + 1);

            // causal mask near diagonal
            if (kb * 64 + 63 > qbase + wb) {
                #pragma unroll
                for (int nt = 0; nt < 8; nt++) {
                    int col = kb * 64 + nt * 8 + 2 * t;
                    if (col     > row0)          s0[nt][0] = -1e30f;
                    if (col + 1 > row0)          s0[nt][1] = -1e30f;
                    if (col     > row0 + 8)      s0[nt][2] = -1e30f;
                    if (col + 1 > row0 + 8)      s0[nt][3] = -1e30f;
                    if (col     > row0 + 16)     s1[nt][0] = -1e30f;
                    if (col + 1 > row0 + 16)     s1[nt][1] = -1e30f;
                    if (col     > row0 + 24)     s1[nt][2] = -1e30f;
                    if (col + 1 > row0 + 24)     s1[nt][3] = -1e30f;
                }
            }

            // ---- online softmax, both tiles ----
            float b00 = -1e30f, b01 = -1e30f, b10 = -1e30f, b11 = -1e30f;
            #pragma unroll
            for (int nt = 0; nt < 8; nt++) {
                b00 = fmaxf(b00, fmaxf(s0[nt][0], s0[nt][1]));
                b01 = fmaxf(b01, fmaxf(s0[nt][2], s0[nt][3]));
                b10 = fmaxf(b10, fmaxf(s1[nt][0], s1[nt][1]));
                b11 = fmaxf(b11, fmaxf(s1[nt][2], s1[nt][3]));
            }
            #pragma unroll
            for (int d = 1; d <= 2; d <<= 1) {
                b00 = fmaxf(b00, __shfl_xor_sync(0xffffffffu, b00, d));
                b01 = fmaxf(b01, __shfl_xor_sync(0xffffffffu, b01, d));
                b10 = fmaxf(b10, __shfl_xor_sync(0xffffffffu, b10, d));
                b11 = fmaxf(b11, __shfl_xor_sync(0xffffffffu, b11, d));
            }

            float n00 = fmaxf(m00, b00), n01 = fmaxf(m01, b01);
            float n10 = fmaxf(m10, b10), n11 = fmaxf(m11, b11);
            float c00 = exp2f((m00 - n00) * L2E), c01 = exp2f((m01 - n01) * L2E);
            float c10 = exp2f((m10 - n10) * L2E), c11 = exp2f((m11 - n11) * L2E);

            float s00 = 0.f, s01 = 0.f, s10 = 0.f, s11 = 0.f;
            float* pw00 = Ps + (wb + g) * QP + 2 * t;
            float* pw01 = Ps + (wb + g + 8) * QP + 2 * t;
            float* pw10 = Ps + (wb + 16 + g) * QP + 2 * t;
            float* pw11 = Ps + (wb + 16 + g + 8) * QP + 2 * t;
            #pragma unroll
            for (int nt = 0; nt < 8; nt++) {
                float p0 = exp2f((s0[nt][0] - n00) * L2E);
                float p1 = exp2f((s0[nt][1] - n00) * L2E);
                float p2 = exp2f((s0[nt][2] - n01) * L2E);
                float p3 = exp2f((s0[nt][3] - n01) * L2E);
                float q0 = exp2f((s1[nt][0] - n10) * L2E);
                float q1 = exp2f((s1[nt][1] - n10) * L2E);
                float q2 = exp2f((s1[nt][2] - n11) * L2E);
                float q3 = exp2f((s1[nt][3] - n11) * L2E);
                s00 += p0 + p1; s01 += p2 + p3;
                s10 += q0 + q1; s11 += q2 + q3;
                *(float2*)(pw00 + nt * 8) = make_float2(__uint_as_float(f2tf32(p0)), __uint_as_float(f2tf32(p1)));
                *(float2*)(pw01 + nt * 8) = make_float2(__uint_as_float(f2tf32(p2)), __uint_as_float(f2tf32(p3)));
                *(float2*)(pw10 + nt * 8) = make_float2(__uint_as_float(f2tf32(q0)), __uint_as_float(f2tf32(q1)));
                *(float2*)(pw11 + nt * 8) = make_float2(__uint_as_float(f2tf32(q2)), __uint_as_float(f2tf32(q3)));
            }
            #pragma unroll
            for (int d = 1; d <= 2; d <<= 1) {
                s00 += __shfl_xor_sync(0xffffffffu, s00, d);
                s01 += __shfl_xor_sync(0xffffffffu, s01, d);
                s10 += __shfl_xor_sync(0xffffffffu, s10, d);
                s11 += __shfl_xor_sync(0xffffffffu, s11, d);
            }
            l00 = l00 * c00 + s00; l01 = l01 * c01 + s01;
            l10 = l10 * c10 + s10; l11 = l11 * c11 + s11;
            m00 = n00; m01 = n01; m10 = n10; m11 = n11;

            #pragma unroll
            for (int nt = 0; nt < 8; nt++) {
                o0[nt][0] *= c00; o0[nt][1] *= c00;
                o0[nt][2] *= c01; o0[nt][3] *= c01;
                o1[nt][0] *= c10; o1[nt][1] *= c10;
                o1[nt][2] *= c11; o1[nt][3] *= c11;
            }

            __syncwarp();

            // ---- PV for both tiles, sharing V fragments ----
            const float* pr0 = Ps + (wb + g) * QP + t;
            const float* pr1 = Ps + (wb + 16 + g) * QP + t;
            #pragma unroll
            for (int kt = 0; kt < 8; kt++) {
                uint32_t ap0[4], ap1[4];
                ap0[0] = __float_as_uint(pr0[kt * 8]);
                ap0[1] = __float_as_uint(pr0[8 * QP + kt * 8]);
                ap0[2] = __float_as_uint(pr0[kt * 8 + 4]);
                ap0[3] = __float_as_uint(pr0[8 * QP + kt * 8 + 4]);
                ap1[0] = __float_as_uint(pr1[kt * 8]);
                ap1[1] = __float_as_uint(pr1[8 * QP + kt * 8]);
                ap1[2] = __float_as_uint(pr1[kt * 8 + 4]);
                ap1[3] = __float_as_uint(pr1[8 * QP + kt * 8 + 4]);
                #pragma unroll
                for (int nt = 0; nt < 8; nt++) {
                    uint32_t bv[2];
                    const float* vp = Vs + (kt * 8 + t) * VP + nt * 8 + g;
                    bv[0] = __float_as_uint(vp[0]);
                    bv[1] = __float_as_uint(vp[4 * VP]);
                    mma8(o0[nt], ap0, bv);
                    mma8(o1[nt], ap1, bv);
                }
            }
            __syncwarp();
        } else {
            if (kb + 1 < nkb) gload(kb + 1);
        }

        __syncthreads();                 // all reads of Ks/Vs complete
        if (kb + 1 < nkb) {
            sts_kv();
            __syncthreads();
        }
    }

    // ---- write out: out[b][s][h*64 + d] ----
    const float i00 = 1.f / l00, i01 = 1.f / l01;
    const float i10 = 1.f / l10, i11 = 1.f / l11;
    float* w00 = out + ((size_t)b * SEQ + row0) * DM + h * HD + 2 * t;
    float* w01 = out + ((size_t)b * SEQ + row0 + 8) * DM + h * HD + 2 * t;
    float* w10 = out + ((size_t)b * SEQ + row0 + 16) * DM + h * HD + 2 * t;
    float* w11 = out + ((size_t)b * SEQ + row0 + 24) * DM + h * HD + 2 * t;
    #pragma unroll
    for (int nt = 0; nt < 8; nt++) {
        *(float2*)(w00 + nt * 8) = make_float2(o0[nt][0] * i00, o0[nt][1] * i00);
        *(float2*)(w01 + nt * 8) = make_float2(o0[nt][2] * i01, o0[nt][3] * i01);
        *(float2*)(w10 + nt * 8) = make_float2(o1[nt][0] * i10, o1[nt][1] * i10);
        *(float2*)(w11 + nt * 8) = make_float2(o1[nt][2] * i11, o1[nt][3] * i11);
    }
}

// ---------------------------------------------------------------------------
extern "C" void kernel_launch(void* const* d_in, const int* in_sizes, int n_in,
                              void* d_out, int out_size)
{
    (void)in_sizes; (void)n_in; (void)out_size;
    const float* x    = (const float*)d_in[0];   // [B, S, D]
    const float* Wqkv = (const float*)d_in[1];   // [D, 3D]
    const float* bqkv = (const float*)d_in[2];   // [3D]
    float* out = (float*)d_out;                  // [B, S, D]

    cvt_prepass<<<1184, 256>>>(x, Wqkv);

    const int gemm_smem = (3 * STAGE_A + 3 * STAGE_B) * 4;       // 87552 B
    cudaFuncSetAttribute(qkv_gemm_mma, cudaFuncAttributeMaxDynamicSharedMemorySize, gemm_smem);
    dim3 ggrid(N_TOT / TNG, M_TOT / TMG);        // (24, 32)
    qkv_gemm_mma<<<ggrid, 256, gemm_smem>>>(bqkv);

    const int attn_smem = (CTAQ * QP + 64 * QP + 64 * VP) * 4;   // 105472 B
    cudaFuncSetAttribute(attn_mma, cudaFuncAttributeMaxDynamicSharedMemorySize, attn_smem);
    dim3 agrid(SEQ / CTAQ, NH, BZ);              // (8, 16, 4)
    attn_mma<<<agrid, 256, attn_smem>>>(out);
}

// round 8
// speedup vs baseline: 6.9011x; 1.8592x over previous
#include <cuda_runtime.h>
#include <cuda_fp16.h>
#include <cstdint>

// Problem constants
#define BZ 4
#define SEQ 2048
#define DM 1024
#define NH 16
#define HD 64
#define M_TOT 8192
#define N_TOT 3072

// Scratch (fp16)
__device__ __half g_Qh[BZ*NH*SEQ*HD];
__device__ __half g_Kh[BZ*NH*SEQ*HD];
__device__ __half g_Vh[BZ*NH*SEQ*HD];
__device__ __half g_Xh[M_TOT*DM];      // fp16 x
__device__ __half g_Wt[(size_t)N_TOT*DM];  // fp16 W transposed: [n][k]

// ---------------------------------------------------------------------------
// helpers
// ---------------------------------------------------------------------------
__device__ __forceinline__ void mma16(float* c, const uint32_t* a, uint32_t b0, uint32_t b1){
    asm volatile("mma.sync.aligned.m16n8k16.row.col.f32.f16.f16.f32 "
        "{%0,%1,%2,%3}, {%4,%5,%6,%7}, {%8,%9}, {%0,%1,%2,%3};"
        : "+f"(c[0]), "+f"(c[1]), "+f"(c[2]), "+f"(c[3])
        : "r"(a[0]), "r"(a[1]), "r"(a[2]), "r"(a[3]), "r"(b0), "r"(b1));
}
__device__ __forceinline__ void ldsm4(uint32_t* r, uint32_t addr){
    asm volatile("ldmatrix.sync.aligned.m8n8.x4.shared.b16 {%0,%1,%2,%3}, [%4];"
        : "=r"(r[0]), "=r"(r[1]), "=r"(r[2]), "=r"(r[3]) : "r"(addr));
}
__device__ __forceinline__ void ldsm4t(uint32_t* r, uint32_t addr){
    asm volatile("ldmatrix.sync.aligned.m8n8.x4.trans.shared.b16 {%0,%1,%2,%3}, [%4];"
        : "=r"(r[0]), "=r"(r[1]), "=r"(r[2]), "=r"(r[3]) : "r"(addr));
}
__device__ __forceinline__ uint32_t pack2(float lo, float hi){
    uint32_t r; asm("cvt.rn.f16x2.f32 %0, %1, %2;" : "=r"(r) : "f"(hi), "f"(lo)); return r;
}
__device__ __forceinline__ uint32_t smem_u32(const void* p){
    uint32_t a;
    asm("{ .reg .u64 t; cvta.to.shared.u64 t, %1; cvt.u32.u64 %0, t; }" : "=r"(a) : "l"(p));
    return a;
}
__device__ __forceinline__ void cp16(uint32_t dst, const void* src){
    asm volatile("cp.async.cg.shared.global [%0], [%1], 16;" :: "r"(dst), "l"(src));
}
#define CP_COMMIT() asm volatile("cp.async.commit_group;" ::: "memory")
#define CP_WAIT(n)  asm volatile("cp.async.wait_group %0;" :: "n"(n) : "memory")

// ---------------------------------------------------------------------------
// Prepass: x -> fp16; W -> fp16 transposed [n][k]
// ---------------------------------------------------------------------------
__global__ __launch_bounds__(256) void cvt_x(const float* __restrict__ x)
{
    const size_t n4 = (size_t)M_TOT * DM / 4;
    size_t stride = (size_t)gridDim.x * blockDim.x;
    for (size_t i = (size_t)blockIdx.x * blockDim.x + threadIdx.x; i < n4; i += stride) {
        float4 v = ((const float4*)x)[i];
        __half2* o = (__half2*)(g_Xh + i * 4);
        o[0] = __floats2half2_rn(v.x, v.y);
        o[1] = __floats2half2_rn(v.z, v.w);
    }
}
__global__ __launch_bounds__(256) void cvt_w(const float* __restrict__ W)
{
    __shared__ float tile[32][33];
    const int n0 = blockIdx.x * 32, k0 = blockIdx.y * 32;
    const int tx = threadIdx.x & 31, ty = threadIdx.x >> 5;   // 32x8
    #pragma unroll
    for (int j = 0; j < 4; j++)
        tile[ty + 8 * j][tx] = W[(size_t)(k0 + ty + 8 * j) * N_TOT + n0 + tx];
    __syncthreads();
    #pragma unroll
    for (int j = 0; j < 4; j++)
        g_Wt[(size_t)(n0 + ty + 8 * j) * DM + k0 + tx] = __float2half_rn(tile[tx][ty + 8 * j]);
}

// ---------------------------------------------------------------------------
// Kernel 1: QKV GEMM, fp16 mma.sync m16n8k16 + ldmatrix + cp.async 3-stage.
// CTA tile 256x128, BK=32, 8 warps (4M x 2N), warp tile 64x64.
// ---------------------------------------------------------------------------
#define ASTR 40                 // halves per A row (32 + 8 pad)
#define BSTR 40
#define SA_H (256*ASTR)
#define SB_H (128*BSTR)
#define SA_B (SA_H*2)           // 20480 B
#define SB_B (SB_H*2)           // 10240 B

__global__ __launch_bounds__(256, 1) void qkv_gemm(const float* __restrict__ bias)
{
    extern __shared__ __half smh[];
    __half* sA = smh;
    __half* sB = smh + 3 * SA_H;
    const uint32_t uA = smem_u32(sA);
    const uint32_t uB = smem_u32(sB);

    const int tid  = threadIdx.x;
    const int wid  = tid >> 5;
    const int lane = tid & 31;
    const int g = lane >> 2, t = lane & 3;
    const int wrow = wid & 3;
    const int wcol = wid >> 2;
    const int bm = blockIdx.y, bn = blockIdx.x;

    const __half* Ab = g_Xh + (size_t)(bm * 256) * DM;
    const __half* Bb = g_Wt + (size_t)(bn * 128) * DM;

    int arow[4], acol[4];
    #pragma unroll
    for (int l = 0; l < 4; l++) {
        int idx = tid + l * 256;
        arow[l] = idx >> 2;            // 0..255
        acol[l] = (idx & 3) * 8;       // halves
    }
    int brow[2], bcol[2];
    #pragma unroll
    for (int l = 0; l < 2; l++) {
        int idx = tid + l * 256;
        brow[l] = idx >> 2;            // 0..127
        bcol[l] = (idx & 3) * 8;
    }

    auto issue = [&](int slot, int k0) {
        uint32_t pa = uA + slot * SA_B;
        uint32_t pb = uB + slot * SB_B;
        #pragma unroll
        for (int l = 0; l < 4; l++)
            cp16(pa + (arow[l] * ASTR + acol[l]) * 2, Ab + (size_t)arow[l] * DM + k0 + acol[l]);
        #pragma unroll
        for (int l = 0; l < 2; l++)
            cp16(pb + (brow[l] * BSTR + bcol[l]) * 2, Bb + (size_t)brow[l] * DM + k0 + bcol[l]);
    };

    float acc[4][8][4];
    #pragma unroll
    for (int mt = 0; mt < 4; mt++)
        #pragma unroll
        for (int nt = 0; nt < 8; nt++)
            #pragma unroll
            for (int e = 0; e < 4; e++) acc[mt][nt][e] = 0.f;

    issue(0, 0);  CP_COMMIT();
    issue(1, 32); CP_COMMIT();
    CP_WAIT(1);
    __syncthreads();

    // ldmatrix per-thread base addresses (bytes)
    const uint32_t aBase = uA + (wrow * 64 + (lane & 15)) * (ASTR * 2)
                         + ((lane & 16) ? 16 : 0);              // +8 halves
    const uint32_t bBase = uB + (wcol * 64 + (lane & 7) + ((lane & 16) ? 8 : 0)) * (BSTR * 2)
                         + ((lane & 8) ? 16 : 0);

    int slot = 0;
    #pragma unroll 1
    for (int kb = 0; kb < DM / 32; kb++) {
        if (kb + 2 < DM / 32) {
            int ns = slot + 2; if (ns >= 3) ns -= 3;
            issue(ns, (kb + 2) * 32);
            CP_COMMIT();
        }

        #pragma unroll
        for (int kt = 0; kt < 2; kt++) {
            uint32_t af[4][4], bf[4][4];
            #pragma unroll
            for (int mt = 0; mt < 4; mt++)
                ldsm4(af[mt], aBase + slot * SA_B + mt * 16 * (ASTR * 2) + kt * 32);
            #pragma unroll
            for (int ntp = 0; ntp < 4; ntp++)
                ldsm4(bf[ntp], bBase + slot * SB_B + ntp * 16 * (BSTR * 2) + kt * 32);
            #pragma unroll
            for (int mt = 0; mt < 4; mt++)
                #pragma unroll
                for (int nt = 0; nt < 8; nt++)
                    mma16(acc[mt][nt], af[mt], bf[nt >> 1][(nt & 1) * 2], bf[nt >> 1][(nt & 1) * 2 + 1]);
        }

        if (kb + 2 < DM / 32) { CP_WAIT(1); } else { CP_WAIT(0); }
        __syncthreads();
        if (++slot == 3) slot = 0;
    }

    // Epilogue: bias, Q x0.125, half2 scatter
    #pragma unroll
    for (int mt = 0; mt < 4; mt++) {
        #pragma unroll
        for (int nt = 0; nt < 8; nt++) {
            int n0 = bn * 128 + wcol * 64 + nt * 8 + 2 * t;
            float bx = __ldg(&bias[n0]), by = __ldg(&bias[n0 + 1]);
            int h = n0 / 192;
            int r = n0 - h * 192;
            __half* dst = (r < 64) ? g_Qh : ((r < 128) ? g_Kh : g_Vh);
            float scl = (r < 64) ? 0.125f : 1.f;
            #pragma unroll
            for (int half_ = 0; half_ < 2; half_++) {
                int m  = bm * 256 + wrow * 64 + mt * 16 + g + half_ * 8;
                int b_ = m >> 11;
                int s_ = m & 2047;
                size_t o = ((((size_t)b_ * NH + h) * SEQ) + s_) * HD + (r & 63);
                *(__half2*)(dst + o) = __floats2half2_rn((acc[mt][nt][half_ * 2]     + bx) * scl,
                                                         (acc[mt][nt][half_ * 2 + 1] + by) * scl);
            }
        }
    }
}

// ---------------------------------------------------------------------------
// Kernel 2: causal flash attention, fp16 mma + ldmatrix, register-resident P.
// 8 warps x 32 q-rows = 256 q-rows/CTA; KV tiles 64 keys, cp.async dbl-buffer.
// ---------------------------------------------------------------------------
#define QSTR 72
#define KSTR 72
#define KV_B (64*KSTR*2)        // 9216 B per stage per tensor
#define CTAQ 256
#define L2E 1.44269504f

__global__ __launch_bounds__(256, 1) void attn_fa(float* __restrict__ out)
{
    extern __shared__ __half smh[];
    __half* Qs = smh;                       // [256][QSTR]
    __half* Ks = Qs + CTAQ * QSTR;          // [2][64][KSTR]
    __half* Vs = Ks + 2 * 64 * KSTR;        // [2][64][KSTR]
    const uint32_t uQ = smem_u32(Qs);
    const uint32_t uK = smem_u32(Ks);
    const uint32_t uV = smem_u32(Vs);

    const int tid  = threadIdx.x;
    const int wid  = tid >> 5;
    const int lane = tid & 31;
    const int g = lane >> 2, t = lane & 3;
    const int qt = gridDim.x - 1 - blockIdx.x;
    const int h = blockIdx.y, b = blockIdx.z;
    const int wb = wid * 32;
    const int qbase = qt * CTAQ;
    const int row0 = qbase + wb + g;

    const size_t hb = (((size_t)b * NH + h) * SEQ) * HD;
    const int nkb = (qt + 1) * (CTAQ / 64);

    // cp.async mappings
    int kvrow[2], kvcol[2];
    #pragma unroll
    for (int i = 0; i < 2; i++) {
        int idx = tid + i * 256;
        kvrow[i] = idx >> 3;           // 0..63
        kvcol[i] = (idx & 7) * 8;
    }
    auto issueKV = [&](int kb, int slot) {
        const __half* ks = g_Kh + hb + (size_t)kb * 64 * HD;
        const __half* vs = g_Vh + hb + (size_t)kb * 64 * HD;
        #pragma unroll
        for (int i = 0; i < 2; i++) {
            cp16(uK + slot * KV_B + (kvrow[i] * KSTR + kvcol[i]) * 2, ks + kvrow[i] * HD + kvcol[i]);
            cp16(uV + slot * KV_B + (kvrow[i] * KSTR + kvcol[i]) * 2, vs + kvrow[i] * HD + kvcol[i]);
        }
    };

    issueKV(0, 0);
    CP_COMMIT();
    // stage Q
    {
        const __half* qs = g_Qh + hb + (size_t)qbase * HD;
        #pragma unroll
        for (int i = 0; i < 8; i++) {
            int idx = tid + i * 256;
            int r = idx >> 3, c = (idx & 7) * 8;
            cp16(uQ + (r * QSTR + c) * 2, qs + r * HD + c);
        }
    }
    CP_COMMIT();
    CP_WAIT(0);
    __syncthreads();

    // Q fragments: [mt][kt][4]
    uint32_t aq[2][4][4];
    {
        const uint32_t qb = uQ + (wb + (lane & 15)) * (QSTR * 2) + ((lane & 16) ? 16 : 0);
        #pragma unroll
        for (int mt = 0; mt < 2; mt++)
            #pragma unroll
            for (int kt = 0; kt < 4; kt++)
                ldsm4(aq[mt][kt], qb + mt * 16 * (QSTR * 2) + kt * 32);
    }

    float o[2][8][4];
    #pragma unroll
    for (int mt = 0; mt < 2; mt++)
        #pragma unroll
        for (int nt = 0; nt < 8; nt++)
            #pragma unroll
            for (int e = 0; e < 4; e++) o[mt][nt][e] = 0.f;
    float m00 = -1e30f, m01 = -1e30f, m10 = -1e30f, m11 = -1e30f;
    float l00 = 0.f, l01 = 0.f, l10 = 0.f, l11 = 0.f;

    const uint32_t kfOff = ((lane & 7) + ((lane & 16) ? 8 : 0)) * (KSTR * 2) + ((lane & 8) ? 16 : 0);
    const uint32_t vfOff = ((lane & 7) + ((lane & 8) ? 8 : 0)) * (KSTR * 2) + ((lane & 16) ? 16 : 0);

    #pragma unroll 1
    for (int kb = 0; kb < nkb; kb++) {
        const int slot = kb & 1;
        if (kb + 1 < nkb) { issueKV(kb + 1, slot ^ 1); CP_COMMIT(); }
        if (kb + 1 < nkb) { CP_WAIT(1); } else { CP_WAIT(0); }
        __syncthreads();

        if (kb * 64 <= qbase + wb + 31) {
            // ---- QK^T ----
            float s[2][8][4];
            #pragma unroll
            for (int mt = 0; mt < 2; mt++)
                #pragma unroll
                for (int nt = 0; nt < 8; nt++)
                    #pragma unroll
                    for (int e = 0; e < 4; e++) s[mt][nt][e] = 0.f;

            const uint32_t kbase_ = uK + slot * KV_B + kfOff;
            #pragma unroll
            for (int kt = 0; kt < 4; kt++) {
                uint32_t kf[4][4];
                #pragma unroll
                for (int ntp = 0; ntp < 4; ntp++)
                    ldsm4(kf[ntp], kbase_ + ntp * 16 * (KSTR * 2) + kt * 32);
                #pragma unroll
                for (int nt = 0; nt < 8; nt++) {
                    uint32_t b0 = kf[nt >> 1][(nt & 1) * 2], b1 = kf[nt >> 1][(nt & 1) * 2 + 1];
                    mma16(s[0][nt], aq[0][kt], b0, b1);
                    mma16(s[1][nt], aq[1][kt], b0, b1);
                }
            }

            // causal mask near diagonal
            if (kb * 64 + 63 > qbase + wb) {
                #pragma unroll
                for (int nt = 0; nt < 8; nt++) {
                    int col = kb * 64 + nt * 8 + 2 * t;
                    if (col     > row0)      s[0][nt][0] = -1e30f;
                    if (col + 1 > row0)      s[0][nt][1] = -1e30f;
                    if (col     > row0 + 8)  s[0][nt][2] = -1e30f;
                    if (col + 1 > row0 + 8)  s[0][nt][3] = -1e30f;
                    if (col     > row0 + 16) s[1][nt][0] = -1e30f;
                    if (col + 1 > row0 + 16) s[1][nt][1] = -1e30f;
                    if (col     > row0 + 24) s[1][nt][2] = -1e30f;
                    if (col + 1 > row0 + 24) s[1][nt][3] = -1e30f;
                }
            }

            // ---- online softmax ----
            float b00 = -1e30f, b01 = -1e30f, b10 = -1e30f, b11 = -1e30f;
            #pragma unroll
            for (int nt = 0; nt < 8; nt++) {
                b00 = fmaxf(b00, fmaxf(s[0][nt][0], s[0][nt][1]));
                b01 = fmaxf(b01, fmaxf(s[0][nt][2], s[0][nt][3]));
                b10 = fmaxf(b10, fmaxf(s[1][nt][0], s[1][nt][1]));
                b11 = fmaxf(b11, fmaxf(s[1][nt][2], s[1][nt][3]));
            }
            #pragma unroll
            for (int d = 1; d <= 2; d <<= 1) {
                b00 = fmaxf(b00, __shfl_xor_sync(0xffffffffu, b00, d));
                b01 = fmaxf(b01, __shfl_xor_sync(0xffffffffu, b01, d));
                b10 = fmaxf(b10, __shfl_xor_sync(0xffffffffu, b10, d));
                b11 = fmaxf(b11, __shfl_xor_sync(0xffffffffu, b11, d));
            }
            float n00 = fmaxf(m00, b00), n01 = fmaxf(m01, b01);
            float n10 = fmaxf(m10, b10), n11 = fmaxf(m11, b11);
            float c00 = exp2f((m00 - n00) * L2E), c01 = exp2f((m01 - n01) * L2E);
            float c10 = exp2f((m10 - n10) * L2E), c11 = exp2f((m11 - n11) * L2E);

            uint32_t pc[2][8][2];
            float s00 = 0.f, s01 = 0.f, s10 = 0.f, s11 = 0.f;
            #pragma unroll
            for (int nt = 0; nt < 8; nt++) {
                float p0 = exp2f((s[0][nt][0] - n00) * L2E);
                float p1 = exp2f((s[0][nt][1] - n00) * L2E);
                float p2 = exp2f((s[0][nt][2] - n01) * L2E);
                float p3 = exp2f((s[0][nt][3] - n01) * L2E);
                float q0 = exp2f((s[1][nt][0] - n10) * L2E);
                float q1 = exp2f((s[1][nt][1] - n10) * L2E);
                float q2 = exp2f((s[1][nt][2] - n11) * L2E);
                float q3 = exp2f((s[1][nt][3] - n11) * L2E);
                s00 += p0 + p1; s01 += p2 + p3;
                s10 += q0 + q1; s11 += q2 + q3;
                pc[0][nt][0] = pack2(p0, p1);
                pc[0][nt][1] = pack2(p2, p3);
                pc[1][nt][0] = pack2(q0, q1);
                pc[1][nt][1] = pack2(q2, q3);
            }
            #pragma unroll
            for (int d = 1; d <= 2; d <<= 1) {
                s00 += __shfl_xor_sync(0xffffffffu, s00, d);
                s01 += __shfl_xor_sync(0xffffffffu, s01, d);
                s10 += __shfl_xor_sync(0xffffffffu, s10, d);
                s11 += __shfl_xor_sync(0xffffffffu, s11, d);
            }
            l00 = l00 * c00 + s00; l01 = l01 * c01 + s01;
            l10 = l10 * c10 + s10; l11 = l11 * c11 + s11;
            m00 = n00; m01 = n01; m10 = n10; m11 = n11;

            #pragma unroll
            for (int nt = 0; nt < 8; nt++) {
                o[0][nt][0] *= c00; o[0][nt][1] *= c00;
                o[0][nt][2] *= c01; o[0][nt][3] *= c01;
                o[1][nt][0] *= c10; o[1][nt][1] *= c10;
                o[1][nt][2] *= c11; o[1][nt][3] *= c11;
            }

            // ---- PV (P in registers) ----
            const uint32_t vbase_ = uV + slot * KV_B + vfOff;
            #pragma unroll
            for (int kt = 0; kt < 4; kt++) {
                uint32_t vf[4][4];
                #pragma unroll
                for (int ntp = 0; ntp < 4; ntp++)
                    ldsm4t(vf[ntp], vbase_ + kt * 16 * (KSTR * 2) + ntp * 32);
                uint32_t ap0[4] = {pc[0][2*kt][0], pc[0][2*kt][1], pc[0][2*kt+1][0], pc[0][2*kt+1][1]};
                uint32_t ap1[4] = {pc[1][2*kt][0], pc[1][2*kt][1], pc[1][2*kt+1][0], pc[1][2*kt+1][1]};
                #pragma unroll
                for (int nt = 0; nt < 8; nt++) {
                    uint32_t b0 = vf[nt >> 1][(nt & 1) * 2], b1 = vf[nt >> 1][(nt & 1) * 2 + 1];
                    mma16(o[0][nt], ap0, b0, b1);
                    mma16(o[1][nt], ap1, b0, b1);
                }
            }
        }

        __syncthreads();   // all reads of slot done before it is overwritten
    }

    // ---- write out (fp32) ----
    const float i00 = 1.f / l00, i01 = 1.f / l01;
    const float i10 = 1.f / l10, i11 = 1.f / l11;
    float* w00 = out + ((size_t)b * SEQ + row0) * DM + h * HD + 2 * t;
    float* w01 = out + ((size_t)b * SEQ + row0 + 8) * DM + h * HD + 2 * t;
    float* w10 = out + ((size_t)b * SEQ + row0 + 16) * DM + h * HD + 2 * t;
    float* w11 = out + ((size_t)b * SEQ + row0 + 24) * DM + h * HD + 2 * t;
    #pragma unroll
    for (int nt = 0; nt < 8; nt++) {
        *(float2*)(w00 + nt * 8) = make_float2(o[0][nt][0] * i00, o[0][nt][1] * i00);
        *(float2*)(w01 + nt * 8) = make_float2(o[0][nt][2] * i01, o[0][nt][3] * i01);
        *(float2*)(w10 + nt * 8) = make_float2(o[1][nt][0] * i10, o[1][nt][1] * i10);
        *(float2*)(w11 + nt * 8) = make_float2(o[1][nt][2] * i11, o[1][nt][3] * i11);
    }
}

// ---------------------------------------------------------------------------
extern "C" void kernel_launch(void* const* d_in, const int* in_sizes, int n_in,
                              void* d_out, int out_size)
{
    (void)in_sizes; (void)n_in; (void)out_size;
    const float* x    = (const float*)d_in[0];
    const float* Wqkv = (const float*)d_in[1];
    const float* bqkv = (const float*)d_in[2];
    float* out = (float*)d_out;

    cvt_x<<<2048, 256>>>(x);
    cvt_w<<<dim3(N_TOT / 32, DM / 32), 256>>>(Wqkv);

    const int gemm_smem = 3 * (SA_B + SB_B);                 // 92160 B
    cudaFuncSetAttribute(qkv_gemm, cudaFuncAttributeMaxDynamicSharedMemorySize, gemm_smem);
    dim3 ggrid(N_TOT / 128, M_TOT / 256);                    // (24, 32)
    qkv_gemm<<<ggrid, 256, gemm_smem>>>(bqkv);

    const int attn_smem = (CTAQ * QSTR + 4 * 64 * KSTR) * 2; // 73728 B
    cudaFuncSetAttribute(attn_fa, cudaFuncAttributeMaxDynamicSharedMemorySize, attn_smem);
    dim3 agrid(SEQ / CTAQ, NH, BZ);                          // (8, 16, 4)
    attn_fa<<<agrid, 256, attn_smem>>>(out);
}

// round 9
// speedup vs baseline: 7.2117x; 1.0450x over previous
#include <cuda_runtime.h>
#include <cuda_fp16.h>
#include <cstdint>

// Problem constants
#define BZ 4
#define SEQ 2048
#define DM 1024
#define NH 16
#define HD 64
#define M_TOT 8192
#define N_TOT 3072

// Scratch (fp16)
__device__ __half g_Qh[BZ*NH*SEQ*HD];
__device__ __half g_Kh[BZ*NH*SEQ*HD];
__device__ __half g_Vh[BZ*NH*SEQ*HD];
__device__ __half g_Xh[M_TOT*DM];
__device__ __half g_Wt[(size_t)N_TOT*DM];   // W transposed [n][k]

// ---------------------------------------------------------------------------
// helpers
// ---------------------------------------------------------------------------
__device__ __forceinline__ void mma16(float* c, const uint32_t* a, uint32_t b0, uint32_t b1){
    asm volatile("mma.sync.aligned.m16n8k16.row.col.f32.f16.f16.f32 "
        "{%0,%1,%2,%3}, {%4,%5,%6,%7}, {%8,%9}, {%0,%1,%2,%3};"
        : "+f"(c[0]), "+f"(c[1]), "+f"(c[2]), "+f"(c[3])
        : "r"(a[0]), "r"(a[1]), "r"(a[2]), "r"(a[3]), "r"(b0), "r"(b1));
}
__device__ __forceinline__ void ldsm4(uint32_t* r, uint32_t addr){
    asm volatile("ldmatrix.sync.aligned.m8n8.x4.shared.b16 {%0,%1,%2,%3}, [%4];"
        : "=r"(r[0]), "=r"(r[1]), "=r"(r[2]), "=r"(r[3]) : "r"(addr));
}
__device__ __forceinline__ void ldsm4t(uint32_t* r, uint32_t addr){
    asm volatile("ldmatrix.sync.aligned.m8n8.x4.trans.shared.b16 {%0,%1,%2,%3}, [%4];"
        : "=r"(r[0]), "=r"(r[1]), "=r"(r[2]), "=r"(r[3]) : "r"(addr));
}
__device__ __forceinline__ uint32_t pack2(float lo, float hi){
    uint32_t r; asm("cvt.rn.f16x2.f32 %0, %1, %2;" : "=r"(r) : "f"(hi), "f"(lo)); return r;
}
__device__ __forceinline__ uint32_t smem_u32(const void* p){
    uint32_t a;
    asm("{ .reg .u64 t; cvta.to.shared.u64 t, %1; cvt.u32.u64 %0, t; }" : "=r"(a) : "l"(p));
    return a;
}
__device__ __forceinline__ void cp16(uint32_t dst, const void* src){
    asm volatile("cp.async.cg.shared.global [%0], [%1], 16;" :: "r"(dst), "l"(src));
}
#define CP_COMMIT() asm volatile("cp.async.commit_group;" ::: "memory")
#define CP_WAIT(n)  asm volatile("cp.async.wait_group %0;" :: "n"(n) : "memory")

// ---------------------------------------------------------------------------
// Prepass
// ---------------------------------------------------------------------------
__global__ __launch_bounds__(256) void cvt_x(const float* __restrict__ x)
{
    const size_t n4 = (size_t)M_TOT * DM / 4;
    const size_t gid = (size_t)blockIdx.x * blockDim.x + threadIdx.x;
    const size_t stride = (size_t)gridDim.x * blockDim.x;
    for (size_t i = gid * 4; i < n4; i += stride * 4) {
        float4 v0 = ((const float4*)x)[i];
        float4 v1 = ((const float4*)x)[i + 1];
        float4 v2 = ((const float4*)x)[i + 2];
        float4 v3 = ((const float4*)x)[i + 3];
        __half2* o = (__half2*)(g_Xh + i * 4);
        o[0] = __floats2half2_rn(v0.x, v0.y); o[1] = __floats2half2_rn(v0.z, v0.w);
        o[2] = __floats2half2_rn(v1.x, v1.y); o[3] = __floats2half2_rn(v1.z, v1.w);
        o[4] = __floats2half2_rn(v2.x, v2.y); o[5] = __floats2half2_rn(v2.z, v2.w);
        o[6] = __floats2half2_rn(v3.x, v3.y); o[7] = __floats2half2_rn(v3.z, v3.w);
    }
}
__global__ __launch_bounds__(256) void cvt_w(const float* __restrict__ W)
{
    __shared__ float tile[32][33];
    const int n0 = blockIdx.x * 32, k0 = blockIdx.y * 32;
    const int tx = threadIdx.x & 31, ty = threadIdx.x >> 5;
    #pragma unroll
    for (int j = 0; j < 4; j++)
        tile[ty + 8 * j][tx] = W[(size_t)(k0 + ty + 8 * j) * N_TOT + n0 + tx];
    __syncthreads();
    #pragma unroll
    for (int j = 0; j < 4; j++)
        g_Wt[(size_t)(n0 + ty + 8 * j) * DM + k0 + tx] = __float2half_rn(tile[tx][ty + 8 * j]);
}

// ---------------------------------------------------------------------------
// Kernel 1: QKV GEMM, fp16 mma + ldmatrix + 4-stage cp.async.
// CTA tile 256x128, BK=32, 8 warps (4M x 2N), warp tile 64x64.
// ---------------------------------------------------------------------------
#define ASTR 40
#define BSTR 40
#define SA_H (256*ASTR)
#define SB_H (128*BSTR)
#define SA_B (SA_H*2)
#define SB_B (SB_H*2)
#define NKB  (DM/32)            // 32
#define NSTG 4

__global__ __launch_bounds__(256, 1) void qkv_gemm(const float* __restrict__ bias)
{
    extern __shared__ __half smh[];
    __half* sA = smh;
    __half* sB = smh + NSTG * SA_H;
    const uint32_t uA = smem_u32(sA);
    const uint32_t uB = smem_u32(sB);

    const int tid  = threadIdx.x;
    const int wid  = tid >> 5;
    const int lane = tid & 31;
    const int g = lane >> 2, t = lane & 3;
    const int wrow = wid & 3;
    const int wcol = wid >> 2;
    const int bm = blockIdx.y, bn = blockIdx.x;

    const __half* Ab = g_Xh + (size_t)(bm * 256) * DM;
    const __half* Bb = g_Wt + (size_t)(bn * 128) * DM;

    int arow[4], acol[4];
    #pragma unroll
    for (int l = 0; l < 4; l++) {
        int idx = tid + l * 256;
        arow[l] = idx >> 2;
        acol[l] = (idx & 3) * 8;
    }
    int brow[2], bcol[2];
    #pragma unroll
    for (int l = 0; l < 2; l++) {
        int idx = tid + l * 256;
        brow[l] = idx >> 2;
        bcol[l] = (idx & 3) * 8;
    }

    auto issue = [&](int slot, int k0) {
        uint32_t pa = uA + slot * SA_B;
        uint32_t pb = uB + slot * SB_B;
        #pragma unroll
        for (int l = 0; l < 4; l++)
            cp16(pa + (arow[l] * ASTR + acol[l]) * 2, Ab + (size_t)arow[l] * DM + k0 + acol[l]);
        #pragma unroll
        for (int l = 0; l < 2; l++)
            cp16(pb + (brow[l] * BSTR + bcol[l]) * 2, Bb + (size_t)brow[l] * DM + k0 + bcol[l]);
    };

    float acc[4][8][4];
    #pragma unroll
    for (int mt = 0; mt < 4; mt++)
        #pragma unroll
        for (int nt = 0; nt < 8; nt++)
            #pragma unroll
            for (int e = 0; e < 4; e++) acc[mt][nt][e] = 0.f;

    issue(0, 0);  CP_COMMIT();
    issue(1, 32); CP_COMMIT();
    issue(2, 64); CP_COMMIT();
    CP_WAIT(2);                     // slot 0 ready
    __syncthreads();

    const uint32_t aBase = uA + (wrow * 64 + (lane & 15)) * (ASTR * 2) + ((lane & 16) ? 16 : 0);
    const uint32_t bBase = uB + (wcol * 64 + (lane & 7) + ((lane & 16) ? 8 : 0)) * (BSTR * 2)
                         + ((lane & 8) ? 16 : 0);

    int slot = 0;
    #pragma unroll 1
    for (int kb = 0; kb < NKB; kb++) {
        // batch ALL fragment loads for this k-block (16 ldsm), then mma burst
        uint32_t af[2][4][4], bf[2][4][4];
        #pragma unroll
        for (int kt = 0; kt < 2; kt++) {
            #pragma unroll
            for (int mt = 0; mt < 4; mt++)
                ldsm4(af[kt][mt], aBase + slot * SA_B + mt * 16 * (ASTR * 2) + kt * 32);
            #pragma unroll
            for (int ntp = 0; ntp < 4; ntp++)
                ldsm4(bf[kt][ntp], bBase + slot * SB_B + ntp * 16 * (BSTR * 2) + kt * 32);
        }

        if (kb + 3 < NKB) {
            int ns = slot + 3; if (ns >= NSTG) ns -= NSTG;
            issue(ns, (kb + 3) * 32);
            CP_COMMIT();
        }

        #pragma unroll
        for (int kt = 0; kt < 2; kt++)
            #pragma unroll
            for (int mt = 0; mt < 4; mt++)
                #pragma unroll
                for (int nt = 0; nt < 8; nt++)
                    mma16(acc[mt][nt], af[kt][mt],
                          bf[kt][nt >> 1][(nt & 1) * 2], bf[kt][nt >> 1][(nt & 1) * 2 + 1]);

        // ensure slot kb+1 complete before next iteration reads it
        if (kb + 3 < NKB)      { CP_WAIT(2); }
        else if (kb + 2 < NKB) { CP_WAIT(1); }
        else if (kb + 1 < NKB) { CP_WAIT(0); }
        __syncthreads();
        if (++slot == NSTG) slot = 0;
    }

    // Epilogue
    #pragma unroll
    for (int nt = 0; nt < 8; nt++) {
        int n0 = bn * 128 + wcol * 64 + nt * 8 + 2 * t;
        float bx = __ldg(&bias[n0]), by = __ldg(&bias[n0 + 1]);
        int h = n0 / 192;
        int r = n0 - h * 192;
        __half* dst = (r < 64) ? g_Qh : ((r < 128) ? g_Kh : g_Vh);
        float scl = (r < 64) ? 0.125f : 1.f;
        #pragma unroll
        for (int mt = 0; mt < 4; mt++) {
            #pragma unroll
            for (int half_ = 0; half_ < 2; half_++) {
                int m  = bm * 256 + wrow * 64 + mt * 16 + g + half_ * 8;
                int b_ = m >> 11;
                int s_ = m & 2047;
                size_t o = ((((size_t)b_ * NH + h) * SEQ) + s_) * HD + (r & 63);
                *(__half2*)(dst + o) = __floats2half2_rn((acc[mt][nt][half_ * 2]     + bx) * scl,
                                                         (acc[mt][nt][half_ * 2 + 1] + by) * scl);
            }
        }
    }
}

// ---------------------------------------------------------------------------
// Kernel 2: causal flash attention, fp16 mma + ldmatrix, register-resident P.
// (unchanged from round 8)
// ---------------------------------------------------------------------------
#define QSTR 72
#define KSTR 72
#define KV_B (64*KSTR*2)
#define CTAQ 256
#define L2E 1.44269504f

__global__ __launch_bounds__(256, 1) void attn_fa(float* __restrict__ out)
{
    extern __shared__ __half smh[];
    __half* Qs = smh;
    __half* Ks = Qs + CTAQ * QSTR;
    __half* Vs = Ks + 2 * 64 * KSTR;
    const uint32_t uQ = smem_u32(Qs);
    const uint32_t uK = smem_u32(Ks);
    const uint32_t uV = smem_u32(Vs);

    const int tid  = threadIdx.x;
    const int wid  = tid >> 5;
    const int lane = tid & 31;
    const int g = lane >> 2, t = lane & 3;
    const int qt = gridDim.x - 1 - blockIdx.x;
    const int h = blockIdx.y, b = blockIdx.z;
    const int wb = wid * 32;
    const int qbase = qt * CTAQ;
    const int row0 = qbase + wb + g;

    const size_t hb = (((size_t)b * NH + h) * SEQ) * HD;
    const int nkb = (qt + 1) * (CTAQ / 64);

    int kvrow[2], kvcol[2];
    #pragma unroll
    for (int i = 0; i < 2; i++) {
        int idx = tid + i * 256;
        kvrow[i] = idx >> 3;
        kvcol[i] = (idx & 7) * 8;
    }
    auto issueKV = [&](int kb, int slot) {
        const __half* ks = g_Kh + hb + (size_t)kb * 64 * HD;
        const __half* vs = g_Vh + hb + (size_t)kb * 64 * HD;
        #pragma unroll
        for (int i = 0; i < 2; i++) {
            cp16(uK + slot * KV_B + (kvrow[i] * KSTR + kvcol[i]) * 2, ks + kvrow[i] * HD + kvcol[i]);
            cp16(uV + slot * KV_B + (kvrow[i] * KSTR + kvcol[i]) * 2, vs + kvrow[i] * HD + kvcol[i]);
        }
    };

    issueKV(0, 0);
    CP_COMMIT();
    {
        const __half* qs = g_Qh + hb + (size_t)qbase * HD;
        #pragma unroll
        for (int i = 0; i < 8; i++) {
            int idx = tid + i * 256;
            int r = idx >> 3, c = (idx & 7) * 8;
            cp16(uQ + (r * QSTR + c) * 2, qs + r * HD + c);
        }
    }
    CP_COMMIT();
    CP_WAIT(0);
    __syncthreads();

    uint32_t aq[2][4][4];
    {
        const uint32_t qb = uQ + (wb + (lane & 15)) * (QSTR * 2) + ((lane & 16) ? 16 : 0);
        #pragma unroll
        for (int mt = 0; mt < 2; mt++)
            #pragma unroll
            for (int kt = 0; kt < 4; kt++)
                ldsm4(aq[mt][kt], qb + mt * 16 * (QSTR * 2) + kt * 32);
    }

    float o[2][8][4];
    #pragma unroll
    for (int mt = 0; mt < 2; mt++)
        #pragma unroll
        for (int nt = 0; nt < 8; nt++)
            #pragma unroll
            for (int e = 0; e < 4; e++) o[mt][nt][e] = 0.f;
    float m00 = -1e30f, m01 = -1e30f, m10 = -1e30f, m11 = -1e30f;
    float l00 = 0.f, l01 = 0.f, l10 = 0.f, l11 = 0.f;

    const uint32_t kfOff = ((lane & 7) + ((lane & 16) ? 8 : 0)) * (KSTR * 2) + ((lane & 8) ? 16 : 0);
    const uint32_t vfOff = ((lane & 7) + ((lane & 8) ? 8 : 0)) * (KSTR * 2) + ((lane & 16) ? 16 : 0);

    #pragma unroll 1
    for (int kb = 0; kb < nkb; kb++) {
        const int slot = kb & 1;
        if (kb + 1 < nkb) { issueKV(kb + 1, slot ^ 1); CP_COMMIT(); }
        if (kb + 1 < nkb) { CP_WAIT(1); } else { CP_WAIT(0); }
        __syncthreads();

        if (kb * 64 <= qbase + wb + 31) {
            float s[2][8][4];
            #pragma unroll
            for (int mt = 0; mt < 2; mt++)
                #pragma unroll
                for (int nt = 0; nt < 8; nt++)
                    #pragma unroll
                    for (int e = 0; e < 4; e++) s[mt][nt][e] = 0.f;

            const uint32_t kbase_ = uK + slot * KV_B + kfOff;
            #pragma unroll
            for (int kt = 0; kt < 4; kt++) {
                uint32_t kf[4][4];
                #pragma unroll
                for (int ntp = 0; ntp < 4; ntp++)
                    ldsm4(kf[ntp], kbase_ + ntp * 16 * (KSTR * 2) + kt * 32);
                #pragma unroll
                for (int nt = 0; nt < 8; nt++) {
                    uint32_t b0 = kf[nt >> 1][(nt & 1) * 2], b1 = kf[nt >> 1][(nt & 1) * 2 + 1];
                    mma16(s[0][nt], aq[0][kt], b0, b1);
                    mma16(s[1][nt], aq[1][kt], b0, b1);
                }
            }

            if (kb * 64 + 63 > qbase + wb) {
                #pragma unroll
                for (int nt = 0; nt < 8; nt++) {
                    int col = kb * 64 + nt * 8 + 2 * t;
                    if (col     > row0)      s[0][nt][0] = -1e30f;
                    if (col + 1 > row0)      s[0][nt][1] = -1e30f;
                    if (col     > row0 + 8)  s[0][nt][2] = -1e30f;
                    if (col + 1 > row0 + 8)  s[0][nt][3] = -1e30f;
                    if (col     > row0 + 16) s[1][nt][0] = -1e30f;
                    if (col + 1 > row0 + 16) s[1][nt][1] = -1e30f;
                    if (col     > row0 + 24) s[1][nt][2] = -1e30f;
                    if (col + 1 > row0 + 24) s[1][nt][3] = -1e30f;
                }
            }

            float b00 = -1e30f, b01 = -1e30f, b10 = -1e30f, b11 = -1e30f;
            #pragma unroll
            for (int nt = 0; nt < 8; nt++) {
                b00 = fmaxf(b00, fmaxf(s[0][nt][0], s[0][nt][1]));
                b01 = fmaxf(b01, fmaxf(s[0][nt][2], s[0][nt][3]));
                b10 = fmaxf(b10, fmaxf(s[1][nt][0], s[1][nt][1]));
                b11 = fmaxf(b11, fmaxf(s[1][nt][2], s[1][nt][3]));
            }
            #pragma unroll
            for (int d = 1; d <= 2; d <<= 1) {
                b00 = fmaxf(b00, __shfl_xor_sync(0xffffffffu, b00, d));
                b01 = fmaxf(b01, __shfl_xor_sync(0xffffffffu, b01, d));
                b10 = fmaxf(b10, __shfl_xor_sync(0xffffffffu, b10, d));
                b11 = fmaxf(b11, __shfl_xor_sync(0xffffffffu, b11, d));
            }
            float n00 = fmaxf(m00, b00), n01 = fmaxf(m01, b01);
            float n10 = fmaxf(m10, b10), n11 = fmaxf(m11, b11);
            float c00 = exp2f((m00 - n00) * L2E), c01 = exp2f((m01 - n01) * L2E);
            float c10 = exp2f((m10 - n10) * L2E), c11 = exp2f((m11 - n11) * L2E);

            uint32_t pc[2][8][2];
            float s00 = 0.f, s01 = 0.f, s10 = 0.f, s11 = 0.f;
            #pragma unroll
            for (int nt = 0; nt < 8; nt++) {
                float p0 = exp2f((s[0][nt][0] - n00) * L2E);
                float p1 = exp2f((s[0][nt][1] - n00) * L2E);
                float p2 = exp2f((s[0][nt][2] - n01) * L2E);
                float p3 = exp2f((s[0][nt][3] - n01) * L2E);
                float q0 = exp2f((s[1][nt][0] - n10) * L2E);
                float q1 = exp2f((s[1][nt][1] - n10) * L2E);
                float q2 = exp2f((s[1][nt][2] - n11) * L2E);
                float q3 = exp2f((s[1][nt][3] - n11) * L2E);
                s00 += p0 + p1; s01 += p2 + p3;
                s10 += q0 + q1; s11 += q2 + q3;
                pc[0][nt][0] = pack2(p0, p1);
                pc[0][nt][1] = pack2(p2, p3);
                pc[1][nt][0] = pack2(q0, q1);
                pc[1][nt][1] = pack2(q2, q3);
            }
            #pragma unroll
            for (int d = 1; d <= 2; d <<= 1) {
                s00 += __shfl_xor_sync(0xffffffffu, s00, d);
                s01 += __shfl_xor_sync(0xffffffffu, s01, d);
                s10 += __shfl_xor_sync(0xffffffffu, s10, d);
                s11 += __shfl_xor_sync(0xffffffffu, s11, d);
            }
            l00 = l00 * c00 + s00; l01 = l01 * c01 + s01;
            l10 = l10 * c10 + s10; l11 = l11 * c11 + s11;
            m00 = n00; m01 = n01; m10 = n10; m11 = n11;

            #pragma unroll
            for (int nt = 0; nt < 8; nt++) {
                o[0][nt][0] *= c00; o[0][nt][1] *= c00;
                o[0][nt][2] *= c01; o[0][nt][3] *= c01;
                o[1][nt][0] *= c10; o[1][nt][1] *= c10;
                o[1][nt][2] *= c11; o[1][nt][3] *= c11;
            }

            const uint32_t vbase_ = uV + slot * KV_B + vfOff;
            #pragma unroll
            for (int kt = 0; kt < 4; kt++) {
                uint32_t vf[4][4];
                #pragma unroll
                for (int ntp = 0; ntp < 4; ntp++)
                    ldsm4t(vf[ntp], vbase_ + kt * 16 * (KSTR * 2) + ntp * 32);
                uint32_t ap0[4] = {pc[0][2*kt][0], pc[0][2*kt][1], pc[0][2*kt+1][0], pc[0][2*kt+1][1]};
                uint32_t ap1[4] = {pc[1][2*kt][0], pc[1][2*kt][1], pc[1][2*kt+1][0], pc[1][2*kt+1][1]};
                #pragma unroll
                for (int nt = 0; nt < 8; nt++) {
                    uint32_t b0 = vf[nt >> 1][(nt & 1) * 2], b1 = vf[nt >> 1][(nt & 1) * 2 + 1];
                    mma16(o[0][nt], ap0, b0, b1);
                    mma16(o[1][nt], ap1, b0, b1);
                }
            }
        }

        __syncthreads();
    }

    const float i00 = 1.f / l00, i01 = 1.f / l01;
    const float i10 = 1.f / l10, i11 = 1.f / l11;
    float* w00 = out + ((size_t)b * SEQ + row0) * DM + h * HD + 2 * t;
    float* w01 = out + ((size_t)b * SEQ + row0 + 8) * DM + h * HD + 2 * t;
    float* w10 = out + ((size_t)b * SEQ + row0 + 16) * DM + h * HD + 2 * t;
    float* w11 = out + ((size_t)b * SEQ + row0 + 24) * DM + h * HD + 2 * t;
    #pragma unroll
    for (int nt = 0; nt < 8; nt++) {
        *(float2*)(w00 + nt * 8) = make_float2(o[0][nt][0] * i00, o[0][nt][1] * i00);
        *(float2*)(w01 + nt * 8) = make_float2(o[0][nt][2] * i01, o[0][nt][3] * i01);
        *(float2*)(w10 + nt * 8) = make_float2(o[1][nt][0] * i10, o[1][nt][1] * i10);
        *(float2*)(w11 + nt * 8) = make_float2(o[1][nt][2] * i11, o[1][nt][3] * i11);
    }
}

// ---------------------------------------------------------------------------
extern "C" void kernel_launch(void* const* d_in, const int* in_sizes, int n_in,
                              void* d_out, int out_size)
{
    (void)in_sizes; (void)n_in; (void)out_size;
    const float* x    = (const float*)d_in[0];
    const float* Wqkv = (const float*)d_in[1];
    const float* bqkv = (const float*)d_in[2];
    float* out = (float*)d_out;

    cvt_x<<<592, 256>>>(x);
    cvt_w<<<dim3(N_TOT / 32, DM / 32), 256>>>(Wqkv);

    const int gemm_smem = NSTG * (SA_B + SB_B);              // 122880 B
    cudaFuncSetAttribute(qkv_gemm, cudaFuncAttributeMaxDynamicSharedMemorySize, gemm_smem);
    dim3 ggrid(N_TOT / 128, M_TOT / 256);                    // (24, 32)
    qkv_gemm<<<ggrid, 256, gemm_smem>>>(bqkv);

    const int attn_smem = (CTAQ * QSTR + 4 * 64 * KSTR) * 2; // 73728 B
    cudaFuncSetAttribute(attn_fa, cudaFuncAttributeMaxDynamicSharedMemorySize, attn_smem);
    dim3 agrid(SEQ / CTAQ, NH, BZ);                          // (8, 16, 4)
    attn_fa<<<agrid, 256, attn_smem>>>(out);
}